// round 1
// baseline (speedup 1.0000x reference)
#include <cuda_runtime.h>

#define H_  128
#define W_  256
#define HW  32768
#define C_  64
#define CHW (C_*HW)          // 2,097,152
#define MOFF (2*CHW)         // out tensor elements = 4,194,304

// ---------------- scratch (static device globals; no allocation) -------------
__device__ __align__(16) float g_h1 [4*CHW];       // post conv1+leaky (L0,L1,R0,R1)
__device__ __align__(16) float g_buf[4*CHW];       // residual block output
__device__ __align__(16) float g_Q  [2*HW*C_];     // [b][p][c]
__device__ __align__(16) float g_S  [2*HW*C_];     // [b][p][c]
__device__ __align__(16) float g_R  [2*HW*C_];     // [b][p][c]
__device__ __align__(16) float g_attn[2*HW*C_];    // [b][p][c]

// ---------------- 3x3 conv, 64->64, pad 1 ------------------------------------
// mode 0: in = x_left/x_right, out = g_h1, leaky_relu(0.1)
// mode 1: in = g_h1,           out = g_buf, + residual (x_left/x_right)
__global__ __launch_bounds__(256, 2)
void conv3x3_kernel(const float* __restrict__ xl, const float* __restrict__ xr,
                    const float* __restrict__ w, int mode)
{
    __shared__ __align__(16) float tile[8][10][34];   // 8 cin x (8+2) x (32+2)
    __shared__ __align__(16) float wsm[8][9][64];     // [cin][tap][oc]

    const int n  = blockIdx.z;
    const float* in = (mode == 0)
        ? ((n < 2) ? (xl + n*CHW) : (xr + (n-2)*CHW))
        : (g_h1 + n*CHW);

    const int bx = blockIdx.x * 32, by = blockIdx.y * 8;
    const int tx = threadIdx.x & 31, ty = threadIdx.x >> 5;

    float acc[64];
#pragma unroll
    for (int i = 0; i < 64; i++) acc[i] = 0.f;

    for (int c0 = 0; c0 < 64; c0 += 8) {
        __syncthreads();
        // input tile (zero-padded borders)
        for (int i = threadIdx.x; i < 8*10*34; i += 256) {
            int ci = i / 340, rem = i - ci*340;
            int r  = rem / 34, cc = rem - r*34;
            int gy = by + r - 1, gx = bx + cc - 1;
            float v = 0.f;
            if ((unsigned)gy < (unsigned)H_ && (unsigned)gx < (unsigned)W_)
                v = in[(c0+ci)*HW + gy*W_ + gx];
            tile[ci][r][cc] = v;
        }
        // weights: wsm[ci][tap][oc] <- w[oc][c0+ci][tap]
        for (int i = threadIdx.x; i < 8*9*64; i += 256) {
            int ci = i / 576, rem = i - ci*576;
            int tap = rem >> 6, oc = rem & 63;
            wsm[ci][tap][oc] = w[(oc*64 + c0 + ci)*9 + tap];
        }
        __syncthreads();

#pragma unroll 1
        for (int ci = 0; ci < 8; ci++) {
            float p[9];
#pragma unroll
            for (int dy = 0; dy < 3; dy++)
#pragma unroll
                for (int dx = 0; dx < 3; dx++)
                    p[dy*3+dx] = tile[ci][ty+dy][tx+dx];
#pragma unroll
            for (int o4 = 0; o4 < 16; o4++) {
#pragma unroll
                for (int t = 0; t < 9; t++) {
                    float4 wv = *reinterpret_cast<const float4*>(&wsm[ci][t][o4*4]);
                    acc[o4*4+0] = fmaf(p[t], wv.x, acc[o4*4+0]);
                    acc[o4*4+1] = fmaf(p[t], wv.y, acc[o4*4+1]);
                    acc[o4*4+2] = fmaf(p[t], wv.z, acc[o4*4+2]);
                    acc[o4*4+3] = fmaf(p[t], wv.w, acc[o4*4+3]);
                }
            }
        }
    }

    const int pix = (by+ty)*W_ + bx + tx;
    if (mode == 0) {
        float* outp = g_h1 + n*CHW + pix;
#pragma unroll
        for (int oc = 0; oc < 64; oc++) {
            float v = acc[oc];
            outp[oc*HW] = v > 0.f ? v : 0.1f*v;
        }
    } else {
        const float* res = (n < 2) ? (xl + n*CHW) : (xr + (n-2)*CHW);
        float* outp = g_buf + n*CHW + pix;
#pragma unroll
        for (int oc = 0; oc < 64; oc++)
            outp[oc*HW] = acc[oc] + res[oc*HW + pix];
    }
}

// ---------------- 1x1 conv (64->64) : NCHW in -> [b][p][c] out ---------------
// out_sel: 0 -> g_Q, 1 -> g_S, 2 -> g_R ; in = g_buf + in_off (buf_l or buf_r)
__global__ __launch_bounds__(256, 2)
void gemm1x1_kernel(int in_off, const float* __restrict__ w,
                    const float* __restrict__ bias, int out_sel)
{
    __shared__ __align__(16) float wsm[64][64];   // [ic][oc]
    __shared__ float bsm[64];
    for (int i = threadIdx.x; i < 4096; i += 256) {
        int ic = i >> 6, oc = i & 63;
        wsm[ic][oc] = w[oc*64 + ic];
    }
    if (threadIdx.x < 64) bsm[threadIdx.x] = bias[threadIdx.x];
    __syncthreads();

    const int gp  = blockIdx.x*256 + threadIdx.x;   // 0..2*HW-1
    const int img = gp >> 15, p = gp & (HW-1);
    const float* ip = g_buf + in_off + img*CHW + p;

    float acc[64];
#pragma unroll
    for (int i = 0; i < 64; i++) acc[i] = bsm[i];

#pragma unroll 4
    for (int ic = 0; ic < 64; ic++) {
        float v = ip[ic*HW];
#pragma unroll
        for (int o4 = 0; o4 < 16; o4++) {
            float4 wv = *reinterpret_cast<const float4*>(&wsm[ic][o4*4]);
            acc[o4*4+0] = fmaf(v, wv.x, acc[o4*4+0]);
            acc[o4*4+1] = fmaf(v, wv.y, acc[o4*4+1]);
            acc[o4*4+2] = fmaf(v, wv.z, acc[o4*4+2]);
            acc[o4*4+3] = fmaf(v, wv.w, acc[o4*4+3]);
        }
    }
    float* outp = (out_sel == 0 ? g_Q : (out_sel == 1 ? g_S : g_R)) + (size_t)gp*64;
#pragma unroll
    for (int o4 = 0; o4 < 16; o4++) {
        float4 r = make_float4(acc[o4*4+0], acc[o4*4+1], acc[o4*4+2], acc[o4*4+3]);
        *reinterpret_cast<float4*>(&outp[o4*4]) = r;
    }
}

// ---------------- attention: warp per pixel, K = 16 --------------------------
__global__ __launch_bounds__(256)
void attn_kernel(const int* __restrict__ xxs, const int* __restrict__ yys,
                 float* __restrict__ outM)
{
    const unsigned FULL = 0xffffffffu;
    const int warp = threadIdx.x >> 5, lane = threadIdx.x & 31;
    const int gp = blockIdx.x*8 + warp;          // 0..2*HW-1 (= b*HW + p)
    const int b  = gp >> 15;

    const float2 q = reinterpret_cast<const float2*>(g_Q + (size_t)gp*64)[lane];

    int idx = 0;
    if (lane < 16) {
        int i = gp*16 + lane;
        idx = xxs[i]*W_ + yys[i];
    }
    const float* Sb = g_S + (size_t)b*HW*64;
    const float* Rb = g_R + (size_t)b*HW*64;

    float myscore = -1e30f;
#pragma unroll
    for (int k = 0; k < 16; k++) {
        int id = __shfl_sync(FULL, idx, k);
        float2 kv = reinterpret_cast<const float2*>(Sb + (size_t)id*64)[lane];
        float s = q.x*kv.x + q.y*kv.y;
#pragma unroll
        for (int off = 16; off; off >>= 1) s += __shfl_xor_sync(FULL, s, off);
        if (lane == k) myscore = s;
    }
    // softmax across lanes 0..15 (xor<=8 keeps groups of 16 separate)
    float mx = myscore;
#pragma unroll
    for (int off = 8; off; off >>= 1) mx = fmaxf(mx, __shfl_xor_sync(FULL, mx, off));
    float e = __expf(0.0f) * expf(myscore - mx);
    float sum = e;
#pragma unroll
    for (int off = 8; off; off >>= 1) sum += __shfl_xor_sync(FULL, sum, off);
    float m = e / sum;

    float2 accv = make_float2(0.f, 0.f);
#pragma unroll
    for (int k = 0; k < 16; k++) {
        float mk = __shfl_sync(FULL, m, k);
        int   id = __shfl_sync(FULL, idx, k);
        float2 vv = reinterpret_cast<const float2*>(Rb + (size_t)id*64)[lane];
        accv.x = fmaf(mk, vv.x, accv.x);
        accv.y = fmaf(mk, vv.y, accv.y);
    }
    reinterpret_cast<float2*>(g_attn + (size_t)gp*64)[lane] = accv;
    if (lane < 16) outM[(size_t)gp*16 + lane] = m;
}

// ---------------- fusion 1x1 conv: [attn(64ch) ; x_left(64ch)] -> 64ch -------
__global__ __launch_bounds__(256)
void fuse_kernel(const float* __restrict__ xl, const float* __restrict__ fw,
                 const float* __restrict__ fb, float* __restrict__ out)
{
    __shared__ __align__(16) float tile[256][17];  // attn chunk, padded
    __shared__ __align__(16) float wsm[16][64];    // [icl][oc]
    __shared__ float bsm[64];

    const int t = threadIdx.x;
    if (t < 64) bsm[t] = fb[t];

    const int gp0 = blockIdx.x*256;
    const int gp  = gp0 + t;
    const int img = gp >> 15, p = gp & (HW-1);

    float acc[64];
#pragma unroll
    for (int i = 0; i < 64; i++) acc[i] = 0.f;

    // Part A: ic 0..63 from g_attn (staged through smem, coalesced)
    for (int c0 = 0; c0 < 64; c0 += 16) {
        __syncthreads();
        for (int i = t; i < 4096; i += 256) {
            int px = i >> 4, icl = i & 15;
            tile[px][icl] = g_attn[(size_t)(gp0+px)*64 + c0 + icl];
        }
        for (int i = t; i < 1024; i += 256) {
            int icl = i >> 6, oc = i & 63;
            wsm[icl][oc] = fw[oc*128 + c0 + icl];
        }
        __syncthreads();
#pragma unroll
        for (int icl = 0; icl < 16; icl++) {
            float v = tile[t][icl];
#pragma unroll
            for (int o4 = 0; o4 < 16; o4++) {
                float4 wv = *reinterpret_cast<const float4*>(&wsm[icl][o4*4]);
                acc[o4*4+0] = fmaf(v, wv.x, acc[o4*4+0]);
                acc[o4*4+1] = fmaf(v, wv.y, acc[o4*4+1]);
                acc[o4*4+2] = fmaf(v, wv.z, acc[o4*4+2]);
                acc[o4*4+3] = fmaf(v, wv.w, acc[o4*4+3]);
            }
        }
    }

    // Part B: ic 64..127 from x_left (already coalesced in NCHW)
    const float* xb = xl + img*CHW + p;
    for (int c0 = 0; c0 < 64; c0 += 16) {
        __syncthreads();
        for (int i = t; i < 1024; i += 256) {
            int icl = i >> 6, oc = i & 63;
            wsm[icl][oc] = fw[oc*128 + 64 + c0 + icl];
        }
        __syncthreads();
#pragma unroll
        for (int icl = 0; icl < 16; icl++) {
            float v = xb[(c0+icl)*HW];
#pragma unroll
            for (int o4 = 0; o4 < 16; o4++) {
                float4 wv = *reinterpret_cast<const float4*>(&wsm[icl][o4*4]);
                acc[o4*4+0] = fmaf(v, wv.x, acc[o4*4+0]);
                acc[o4*4+1] = fmaf(v, wv.y, acc[o4*4+1]);
                acc[o4*4+2] = fmaf(v, wv.z, acc[o4*4+2]);
                acc[o4*4+3] = fmaf(v, wv.w, acc[o4*4+3]);
            }
        }
    }

    float* ob = out + img*CHW + p;   // NCHW, coalesced across threads per oc
#pragma unroll
    for (int oc = 0; oc < 64; oc++)
        ob[oc*HW] = acc[oc] + bsm[oc];
}

// -----------------------------------------------------------------------------
extern "C" void kernel_launch(void* const* d_in, const int* in_sizes, int n_in,
                              void* d_out, int out_size)
{
    const float* xl    = (const float*)d_in[0];
    const float* xr    = (const float*)d_in[1];
    const int*   xxs   = (const int*)  d_in[2];
    const int*   yys   = (const int*)  d_in[3];
    // d_in[4] = is_training (always 0 -> tuple output)
    const float* rb_w1 = (const float*)d_in[5];
    const float* rb_w2 = (const float*)d_in[6];
    const float* b1_w  = (const float*)d_in[7];
    const float* b1_b  = (const float*)d_in[8];
    const float* b2_w  = (const float*)d_in[9];
    const float* b2_b  = (const float*)d_in[10];
    const float* b3_w  = (const float*)d_in[11];
    const float* b3_b  = (const float*)d_in[12];
    const float* fus_w = (const float*)d_in[13];
    const float* fus_b = (const float*)d_in[14];
    float* out = (float*)d_out;

    dim3 cgrid(W_/32, H_/8, 4);
    conv3x3_kernel<<<cgrid, 256>>>(xl, xr, rb_w1, 0);     // h1 = leaky(conv(x))
    conv3x3_kernel<<<cgrid, 256>>>(xl, xr, rb_w2, 1);     // buf = conv(h1) + x

    gemm1x1_kernel<<<256, 256>>>(0,     b1_w, b1_b, 0);   // Q from buf_l
    gemm1x1_kernel<<<256, 256>>>(2*CHW, b2_w, b2_b, 1);   // S from buf_r
    gemm1x1_kernel<<<256, 256>>>(2*CHW, b3_w, b3_b, 2);   // R from buf_r

    attn_kernel<<<8192, 256>>>(xxs, yys, out + MOFF);     // attn + M output
    fuse_kernel<<<256, 256>>>(xl, fus_w, fus_b, out);     // final 1x1 fusion
}

// round 2
// speedup vs baseline: 1.4312x; 1.4312x over previous
#include <cuda_runtime.h>

#define H_  128
#define W_  256
#define HW  32768
#define C_  64
#define CHW (C_*HW)          // 2,097,152
#define MOFF (2*CHW)         // out elements = 4,194,304

typedef unsigned long long ull;

// packed f32x2 fma: d = a*b + d  (Blackwell FFMA2, only reachable via PTX)
#define FMA2(d,a,b) asm("fma.rn.f32x2 %0, %1, %2, %0;" : "+l"(d) : "l"(a), "l"(b))

__device__ __forceinline__ ull splat2(float v) {
    ull r; asm("mov.b64 %0, {%1, %1};" : "=l"(r) : "f"(v)); return r;
}
__device__ __forceinline__ void unpack2(float& lo, float& hi, ull p) {
    asm("mov.b64 {%0, %1}, %2;" : "=f"(lo), "=f"(hi) : "l"(p));
}

// ---------------- scratch ----------------------------------------------------
__device__ __align__(16) float g_h1 [4*CHW];
__device__ __align__(16) float g_buf[4*CHW];
__device__ __align__(16) float g_Q  [2*HW*C_];     // [b][p][c]
__device__ __align__(16) float g_S  [2*HW*C_];
__device__ __align__(16) float g_R  [2*HW*C_];
__device__ __align__(16) float g_attn[2*HW*C_];

// ---------------- 3x3 conv, 64->64, pad 1, FFMA2 -----------------------------
// Thread: 2 adjacent pixels (x even) x 32 output channels (oc half).
// mode 0: leaky_relu -> g_h1 ; mode 1: + residual -> g_buf
__global__ __launch_bounds__(256, 2)
void conv3x3_kernel(const float* __restrict__ xl, const float* __restrict__ xr,
                    const float* __restrict__ w, int mode)
{
    __shared__ __align__(16) float tile[8][10][34];
    __shared__ __align__(16) float wsm[8][9][64];     // [cin][tap][oc]

    const int n  = blockIdx.z;
    const float* in = (mode == 0)
        ? ((n < 2) ? (xl + n*CHW) : (xr + (n-2)*CHW))
        : (g_h1 + n*CHW);

    const int bx = blockIdx.x * 32, by = blockIdx.y * 8;
    const int tx = threadIdx.x & 15;          // x-pair index
    const int ty = (threadIdx.x >> 4) & 7;
    const int oh = threadIdx.x >> 7;          // oc half (0/1)

    ull acc0[16], acc1[16];                   // [oc pair] for pixel 0 / pixel 1
#pragma unroll
    for (int i = 0; i < 16; i++) { acc0[i] = 0ull; acc1[i] = 0ull; }

    for (int c0 = 0; c0 < 64; c0 += 8) {
        __syncthreads();
        for (int i = threadIdx.x; i < 8*10*34; i += 256) {
            int ci = i / 340, rem = i - ci*340;
            int r  = rem / 34, cc = rem - r*34;
            int gy = by + r - 1, gx = bx + cc - 1;
            float v = 0.f;
            if ((unsigned)gy < (unsigned)H_ && (unsigned)gx < (unsigned)W_)
                v = in[(c0+ci)*HW + gy*W_ + gx];
            tile[ci][r][cc] = v;
        }
        for (int i = threadIdx.x; i < 8*9*64; i += 256) {
            int ci = i / 576, rem = i - ci*576;
            int tap = rem >> 6, oc = rem & 63;
            wsm[ci][tap][oc] = w[(oc*64 + c0 + ci)*9 + tap];
        }
        __syncthreads();

#pragma unroll 1
        for (int ci = 0; ci < 8; ci++) {
            // pixel splats: sp[dy][k] = splat(tile[ci][ty+dy][2tx+k]), k=0..3
            ull sp[3][4];
#pragma unroll
            for (int dy = 0; dy < 3; dy++) {
                const float2* rp = reinterpret_cast<const float2*>(&tile[ci][ty+dy][2*tx]);
                float2 a = rp[0], b = rp[1];
                sp[dy][0] = splat2(a.x); sp[dy][1] = splat2(a.y);
                sp[dy][2] = splat2(b.x); sp[dy][3] = splat2(b.y);
            }
#pragma unroll
            for (int dy = 0; dy < 3; dy++) {
#pragma unroll
                for (int dx = 0; dx < 3; dx++) {
                    ull b0 = sp[dy][dx];       // pixel 0 value, splat
                    ull b1 = sp[dy][dx+1];     // pixel 1 value, splat
                    const ulonglong2* wp = reinterpret_cast<const ulonglong2*>(
                        &wsm[ci][dy*3+dx][oh*32]);
#pragma unroll
                    for (int j = 0; j < 8; j++) {
                        ulonglong2 wv = wp[j]; // 4 consecutive oc = 2 pairs
                        FMA2(acc0[2*j+0], wv.x, b0);
                        FMA2(acc0[2*j+1], wv.y, b0);
                        FMA2(acc1[2*j+0], wv.x, b1);
                        FMA2(acc1[2*j+1], wv.y, b1);
                    }
                }
            }
        }
    }

    const int pix = (by+ty)*W_ + bx + 2*tx;   // even
    if (mode == 0) {
        float* op = g_h1 + n*CHW + pix;
#pragma unroll
        for (int pi = 0; pi < 16; pi++) {
            float e0,o0,e1,o1;
            unpack2(e0,o0,acc0[pi]); unpack2(e1,o1,acc1[pi]);
            int oce = (oh*32 + 2*pi);
            float2 ve = make_float2(e0 > 0.f ? e0 : 0.1f*e0, e1 > 0.f ? e1 : 0.1f*e1);
            float2 vo = make_float2(o0 > 0.f ? o0 : 0.1f*o0, o1 > 0.f ? o1 : 0.1f*o1);
            *reinterpret_cast<float2*>(&op[(size_t)oce*HW])     = ve;
            *reinterpret_cast<float2*>(&op[(size_t)(oce+1)*HW]) = vo;
        }
    } else {
        const float* res = (n < 2) ? (xl + n*CHW) : (xr + (n-2)*CHW);
        float* op = g_buf + n*CHW + pix;
#pragma unroll
        for (int pi = 0; pi < 16; pi++) {
            float e0,o0,e1,o1;
            unpack2(e0,o0,acc0[pi]); unpack2(e1,o1,acc1[pi]);
            int oce = (oh*32 + 2*pi);
            float2 re = *reinterpret_cast<const float2*>(&res[(size_t)oce*HW + pix]);
            float2 ro = *reinterpret_cast<const float2*>(&res[(size_t)(oce+1)*HW + pix]);
            *reinterpret_cast<float2*>(&op[(size_t)oce*HW])     = make_float2(e0+re.x, e1+re.y);
            *reinterpret_cast<float2*>(&op[(size_t)(oce+1)*HW]) = make_float2(o0+ro.x, o1+ro.y);
        }
    }
}

// ---------------- 1x1 conv (64->64) : NCHW in -> [b][p][c] out, FFMA2 --------
__global__ __launch_bounds__(256, 2)
void gemm1x1_kernel(int in_off, const float* __restrict__ w,
                    const float* __restrict__ bias, int out_sel)
{
    __shared__ __align__(16) float wsm[64][64];   // [ic][oc]
    __shared__ __align__(16) float bsm[64];
    for (int i = threadIdx.x; i < 4096; i += 256) {
        int ic = i >> 6, oc = i & 63;
        wsm[ic][oc] = w[oc*64 + ic];
    }
    if (threadIdx.x < 64) bsm[threadIdx.x] = bias[threadIdx.x];
    __syncthreads();

    const int pp = threadIdx.x & 127;       // pixel pair within block
    const int oh = threadIdx.x >> 7;        // oc half
    const int p0 = blockIdx.x*256 + 2*pp;   // global pixel (even), 0..65535
    const int img = p0 >> 15, p = p0 & (HW-1);
    const float* ip = g_buf + in_off + img*CHW + p;

    ull acc0[16], acc1[16];
#pragma unroll
    for (int pi = 0; pi < 16; pi++) {
        ull b = *reinterpret_cast<const ull*>(&bsm[oh*32 + 2*pi]);
        acc0[pi] = b; acc1[pi] = b;
    }

#pragma unroll 4
    for (int ic = 0; ic < 64; ic++) {
        float2 pv = *reinterpret_cast<const float2*>(&ip[(size_t)ic*HW]);
        ull s0 = splat2(pv.x), s1 = splat2(pv.y);
        const ulonglong2* wp = reinterpret_cast<const ulonglong2*>(&wsm[ic][oh*32]);
#pragma unroll
        for (int j = 0; j < 8; j++) {
            ulonglong2 wv = wp[j];
            FMA2(acc0[2*j+0], wv.x, s0);
            FMA2(acc0[2*j+1], wv.y, s0);
            FMA2(acc1[2*j+0], wv.x, s1);
            FMA2(acc1[2*j+1], wv.y, s1);
        }
    }
    float* ob = (out_sel == 0 ? g_Q : (out_sel == 1 ? g_S : g_R));
    ull* o0 = reinterpret_cast<ull*>(ob + (size_t)p0*64 + oh*32);
    ull* o1 = reinterpret_cast<ull*>(ob + (size_t)(p0+1)*64 + oh*32);
#pragma unroll
    for (int pi = 0; pi < 16; pi++) { o0[pi] = acc0[pi]; o1[pi] = acc1[pi]; }
}

// ---------------- attention: warp per pixel, K = 16 --------------------------
__global__ __launch_bounds__(256)
void attn_kernel(const int* __restrict__ xxs, const int* __restrict__ yys,
                 float* __restrict__ outM)
{
    const unsigned FULL = 0xffffffffu;
    const int warp = threadIdx.x >> 5, lane = threadIdx.x & 31;
    const int gp = blockIdx.x*8 + warp;
    const int b  = gp >> 15;

    const float2 q = reinterpret_cast<const float2*>(g_Q + (size_t)gp*64)[lane];

    int idx = 0;
    if (lane < 16) {
        int i = gp*16 + lane;
        idx = xxs[i]*W_ + yys[i];
    }
    const float* Sb = g_S + (size_t)b*HW*64;
    const float* Rb = g_R + (size_t)b*HW*64;

    float myscore = -1e30f;
#pragma unroll
    for (int k = 0; k < 16; k++) {
        int id = __shfl_sync(FULL, idx, k);
        float2 kv = reinterpret_cast<const float2*>(Sb + (size_t)id*64)[lane];
        float s = q.x*kv.x + q.y*kv.y;
#pragma unroll
        for (int off = 16; off; off >>= 1) s += __shfl_xor_sync(FULL, s, off);
        if (lane == k) myscore = s;
    }
    float mx = myscore;
#pragma unroll
    for (int off = 8; off; off >>= 1) mx = fmaxf(mx, __shfl_xor_sync(FULL, mx, off));
    float e = expf(myscore - mx);
    float sum = e;
#pragma unroll
    for (int off = 8; off; off >>= 1) sum += __shfl_xor_sync(FULL, sum, off);
    float m = e / sum;

    float2 accv = make_float2(0.f, 0.f);
#pragma unroll
    for (int k = 0; k < 16; k++) {
        float mk = __shfl_sync(FULL, m, k);
        int   id = __shfl_sync(FULL, idx, k);
        float2 vv = reinterpret_cast<const float2*>(Rb + (size_t)id*64)[lane];
        accv.x = fmaf(mk, vv.x, accv.x);
        accv.y = fmaf(mk, vv.y, accv.y);
    }
    reinterpret_cast<float2*>(g_attn + (size_t)gp*64)[lane] = accv;
    if (lane < 16) outM[(size_t)gp*16 + lane] = m;
}

// ---------------- fusion 1x1: [attn(64) ; x_left(64)] -> 64, FFMA2 -----------
__global__ __launch_bounds__(256)
void fuse_kernel(const float* __restrict__ xl, const float* __restrict__ fw,
                 const float* __restrict__ fb, float* __restrict__ out)
{
    __shared__ __align__(16) float tile[256][17];
    __shared__ __align__(16) float wsm[16][64];
    __shared__ __align__(16) float bsm[64];

    const int t = threadIdx.x;
    if (t < 64) bsm[t] = fb[t];

    const int pp = t & 127, oh = t >> 7;
    const int gp0 = blockIdx.x*256;
    const int p0  = gp0 + 2*pp;
    const int img = p0 >> 15, p = p0 & (HW-1);

    ull acc0[16], acc1[16];
#pragma unroll
    for (int i = 0; i < 16; i++) { acc0[i] = 0ull; acc1[i] = 0ull; }

    // Part A: ic 0..63 from g_attn (pixel-major, staged via smem)
    for (int c0 = 0; c0 < 64; c0 += 16) {
        __syncthreads();
        for (int i = t; i < 4096; i += 256) {
            int px = i >> 4, icl = i & 15;
            tile[px][icl] = g_attn[(size_t)(gp0+px)*64 + c0 + icl];
        }
        for (int i = t; i < 1024; i += 256) {
            int icl = i >> 6, oc = i & 63;
            wsm[icl][oc] = fw[oc*128 + c0 + icl];
        }
        __syncthreads();
#pragma unroll
        for (int icl = 0; icl < 16; icl++) {
            ull s0 = splat2(tile[2*pp][icl]);
            ull s1 = splat2(tile[2*pp+1][icl]);
            const ulonglong2* wp = reinterpret_cast<const ulonglong2*>(&wsm[icl][oh*32]);
#pragma unroll
            for (int j = 0; j < 8; j++) {
                ulonglong2 wv = wp[j];
                FMA2(acc0[2*j+0], wv.x, s0);
                FMA2(acc0[2*j+1], wv.y, s0);
                FMA2(acc1[2*j+0], wv.x, s1);
                FMA2(acc1[2*j+1], wv.y, s1);
            }
        }
    }

    // Part B: ic 64..127 from x_left (NCHW, adjacent pixels contiguous)
    const float* xb = xl + img*CHW + p;
    for (int c0 = 0; c0 < 64; c0 += 16) {
        __syncthreads();
        for (int i = t; i < 1024; i += 256) {
            int icl = i >> 6, oc = i & 63;
            wsm[icl][oc] = fw[oc*128 + 64 + c0 + icl];
        }
        __syncthreads();
#pragma unroll
        for (int icl = 0; icl < 16; icl++) {
            float2 xv = *reinterpret_cast<const float2*>(&xb[(size_t)(c0+icl)*HW]);
            ull s0 = splat2(xv.x);
            ull s1 = splat2(xv.y);
            const ulonglong2* wp = reinterpret_cast<const ulonglong2*>(&wsm[icl][oh*32]);
#pragma unroll
            for (int j = 0; j < 8; j++) {
                ulonglong2 wv = wp[j];
                FMA2(acc0[2*j+0], wv.x, s0);
                FMA2(acc0[2*j+1], wv.y, s0);
                FMA2(acc1[2*j+0], wv.x, s1);
                FMA2(acc1[2*j+1], wv.y, s1);
            }
        }
    }

    float* ob = out + img*CHW + p;
#pragma unroll
    for (int pi = 0; pi < 16; pi++) {
        float e0,o0,e1,o1;
        unpack2(e0,o0,acc0[pi]); unpack2(e1,o1,acc1[pi]);
        int oce = oh*32 + 2*pi;
        float be = bsm[oce], bo = bsm[oce+1];
        *reinterpret_cast<float2*>(&ob[(size_t)oce*HW])     = make_float2(e0+be, e1+be);
        *reinterpret_cast<float2*>(&ob[(size_t)(oce+1)*HW]) = make_float2(o0+bo, o1+bo);
    }
}

// -----------------------------------------------------------------------------
extern "C" void kernel_launch(void* const* d_in, const int* in_sizes, int n_in,
                              void* d_out, int out_size)
{
    const float* xl    = (const float*)d_in[0];
    const float* xr    = (const float*)d_in[1];
    const int*   xxs   = (const int*)  d_in[2];
    const int*   yys   = (const int*)  d_in[3];
    const float* rb_w1 = (const float*)d_in[5];
    const float* rb_w2 = (const float*)d_in[6];
    const float* b1_w  = (const float*)d_in[7];
    const float* b1_b  = (const float*)d_in[8];
    const float* b2_w  = (const float*)d_in[9];
    const float* b2_b  = (const float*)d_in[10];
    const float* b3_w  = (const float*)d_in[11];
    const float* b3_b  = (const float*)d_in[12];
    const float* fus_w = (const float*)d_in[13];
    const float* fus_b = (const float*)d_in[14];
    float* out = (float*)d_out;

    dim3 cgrid(W_/32, H_/8, 4);
    conv3x3_kernel<<<cgrid, 256>>>(xl, xr, rb_w1, 0);
    conv3x3_kernel<<<cgrid, 256>>>(xl, xr, rb_w2, 1);

    gemm1x1_kernel<<<256, 256>>>(0,     b1_w, b1_b, 0);
    gemm1x1_kernel<<<256, 256>>>(2*CHW, b2_w, b2_b, 1);
    gemm1x1_kernel<<<256, 256>>>(2*CHW, b3_w, b3_b, 2);

    attn_kernel<<<8192, 256>>>(xxs, yys, out + MOFF);
    fuse_kernel<<<256, 256>>>(xl, fus_w, fus_b, out);
}

// round 5
// speedup vs baseline: 2.0299x; 1.4183x over previous
#include <cuda_runtime.h>
#include <cuda_bf16.h>
#include <cstdint>

#define H_  128
#define W_  256
#define HW  32768
#define C_  64
#define CHW (C_*HW)          // 2,097,152
#define MOFF (2*CHW)         // out elements = 4,194,304

typedef unsigned long long ull;

// ---------------- packed f32x2 helpers (scalar-path kernels) -----------------
#define FMA2(d,a,b) asm("fma.rn.f32x2 %0, %1, %2, %0;" : "+l"(d) : "l"(a), "l"(b))
__device__ __forceinline__ ull splat2(float v) {
    ull r; asm("mov.b64 %0, {%1, %1};" : "=l"(r) : "f"(v)); return r;
}
__device__ __forceinline__ void unpack2(float& lo, float& hi, ull p) {
    asm("mov.b64 {%0, %1}, %2;" : "=f"(lo), "=f"(hi) : "l"(p));
}

// ---------------- mma.sync / ldmatrix helpers (baseline PTX, sm_80+) ---------
__device__ __forceinline__ uint32_t smem_u32(const void* p) {
    uint32_t a;
    asm("{ .reg .u64 t; cvta.to.shared.u64 t, %1; cvt.u32.u64 %0, t; }" : "=r"(a) : "l"(p));
    return a;
}
__device__ __forceinline__ void ldsm_x4(uint32_t* r, uint32_t addr) {
    asm volatile("ldmatrix.sync.aligned.m8n8.x4.shared.b16 {%0,%1,%2,%3}, [%4];"
        : "=r"(r[0]), "=r"(r[1]), "=r"(r[2]), "=r"(r[3]) : "r"(addr));
}
__device__ __forceinline__ void mma16816(float* d, const uint32_t* a, const uint32_t* b) {
    asm volatile("mma.sync.aligned.m16n8k16.row.col.f32.bf16.bf16.f32 "
        "{%0,%1,%2,%3}, {%4,%5,%6,%7}, {%8,%9}, {%0,%1,%2,%3};"
        : "+f"(d[0]), "+f"(d[1]), "+f"(d[2]), "+f"(d[3])
        : "r"(a[0]), "r"(a[1]), "r"(a[2]), "r"(a[3]), "r"(b[0]), "r"(b[1]));
}

// ---------------- scratch ----------------------------------------------------
__device__ __align__(16) __nv_bfloat16 g_in_hi [4*HW*C_];   // [img][y][x][ch]
__device__ __align__(16) __nv_bfloat16 g_in_lo [4*HW*C_];
__device__ __align__(16) __nv_bfloat16 g_mid_hi[4*HW*C_];
__device__ __align__(16) __nv_bfloat16 g_mid_lo[4*HW*C_];
__device__ __align__(16) __nv_bfloat16 g_w1_hi[9*64*64];    // [tap][oc][ch]
__device__ __align__(16) __nv_bfloat16 g_w1_lo[9*64*64];
__device__ __align__(16) __nv_bfloat16 g_w2_hi[9*64*64];
__device__ __align__(16) __nv_bfloat16 g_w2_lo[9*64*64];
__device__ __align__(16) float g_buf [4*CHW];               // NCHW
__device__ __align__(16) float g_Q   [2*HW*C_];             // [b][p][c]
__device__ __align__(16) float g_S   [2*HW*C_];
__device__ __align__(16) float g_R   [2*HW*C_];
__device__ __align__(16) float g_attn[2*HW*C_];

// ---------------- prep: fp32 NCHW -> bf16 hi/lo [img][y][x][ch] --------------
__global__ __launch_bounds__(256)
void prep_kernel(const float* __restrict__ xl, const float* __restrict__ xr)
{
    const int gp = blockIdx.x*256 + threadIdx.x;   // 0..4*HW-1
    const int n  = gp >> 15, pix = gp & (HW-1);
    const float* src = ((n < 2) ? (xl + n*CHW) : (xr + (n-2)*CHW)) + pix;

    uint32_t hb[32], lb[32];
#pragma unroll
    for (int j = 0; j < 32; j++) {
        float v0 = src[(size_t)(2*j)*HW];
        float v1 = src[(size_t)(2*j+1)*HW];
        __nv_bfloat16 h0 = __float2bfloat16(v0);
        __nv_bfloat16 h1 = __float2bfloat16(v1);
        __nv_bfloat16 l0 = __float2bfloat16(v0 - __bfloat162float(h0));
        __nv_bfloat16 l1 = __float2bfloat16(v1 - __bfloat162float(h1));
        hb[j] = ((uint32_t)__bfloat16_as_ushort(h1) << 16) | __bfloat16_as_ushort(h0);
        lb[j] = ((uint32_t)__bfloat16_as_ushort(l1) << 16) | __bfloat16_as_ushort(l0);
    }
    uint4* dh = reinterpret_cast<uint4*>(g_in_hi + (size_t)gp*64);
    uint4* dl = reinterpret_cast<uint4*>(g_in_lo + (size_t)gp*64);
    const uint4* sh = reinterpret_cast<const uint4*>(hb);
    const uint4* sl = reinterpret_cast<const uint4*>(lb);
#pragma unroll
    for (int j = 0; j < 8; j++) { dh[j] = sh[j]; dl[j] = sl[j]; }
}

// ---------------- prep weights: fp32 [oc][ci][tap] -> bf16 hi/lo [tap][oc][ci]
__global__ __launch_bounds__(256)
void prep_w_kernel(const float* __restrict__ w1, const float* __restrict__ w2)
{
    const int i = blockIdx.x*256 + threadIdx.x;    // 0..9*4096-1
    if (i >= 9*4096) return;
    const int tap = i >> 12, r = i & 4095;
    const int oc = r >> 6, ci = r & 63;
    const int src = (oc*64 + ci)*9 + tap;
    const int dst = (tap*64 + oc)*64 + ci;
    float v1 = w1[src], v2 = w2[src];
    __nv_bfloat16 h1 = __float2bfloat16(v1);
    __nv_bfloat16 h2 = __float2bfloat16(v2);
    g_w1_hi[dst] = h1;
    g_w1_lo[dst] = __float2bfloat16(v1 - __bfloat162float(h1));
    g_w2_hi[dst] = h2;
    g_w2_lo[dst] = __float2bfloat16(v2 - __bfloat162float(h2));
}

// ---------------- HMMA 3x3 conv ----------------------------------------------
// Tile: M=128 pixels (half row) x N=64 oc. 8 warps: 2(M) x 4(N).
// K = 9 taps x 64 ch, 3 split terms (Ah*Bh, Al*Bh, Ah*Bl).
// smem: A = 3 row-planes x 132 px x 128B (hi + lo), B = per-tap 64oc x 128B (hi+lo)
#define APX   132
#define AROWB (APX*128)               // 16896 bytes per row-plane
#define A_HI  0u
#define A_LO  (3u*AROWB)              // 50688
#define B_HI  (6u*AROWB)              // 101376
#define B_LO  (6u*AROWB + 8192u)
#define SMEM_CONV (6u*AROWB + 16384u) // 117760

__global__ __launch_bounds__(256, 1)
void conv_mma_kernel(const __nv_bfloat16* __restrict__ in_hi,
                     const __nv_bfloat16* __restrict__ in_lo,
                     const __nv_bfloat16* __restrict__ w_hi,
                     const __nv_bfloat16* __restrict__ w_lo,
                     const float* __restrict__ xl, const float* __restrict__ xr,
                     int layer)
{
    extern __shared__ __align__(16) char smem[];
    const uint32_t sb = smem_u32(smem);
    const int tid = threadIdx.x;
    const int lane = tid & 31, warp = tid >> 5;
    const int wm = warp & 1, wn = warp >> 1;
    const int mbase = wm*64, ocb = wn*16;

    const int tile = blockIdx.x;                 // 0..1023
    const int n  = tile >> 8;
    const int y  = (tile >> 1) & 127;
    const int x0 = (tile & 1) * 128;

    // ---- stage A: 3 rows x 130 px x 8 granules(16B), hi & lo, XOR-swizzled --
    for (int i = tid; i < 3*130*8; i += 256) {
        const int r = i / (130*8), rem = i % (130*8);
        const int px = rem >> 3, g = rem & 7;
        const int gy = y + r - 1, gx = x0 + px - 1;
        const bool ok = ((unsigned)gy < (unsigned)H_) && ((unsigned)gx < (unsigned)W_);
        const size_t go = (((size_t)(n*H_ + gy))*W_ + gx)*64 + g*8;
        const uint32_t da = r*AROWB + px*128 + ((g ^ (px & 7)) << 4);
        const uint4 z = make_uint4(0,0,0,0);
        *reinterpret_cast<uint4*>(smem + A_HI + da) =
            ok ? *reinterpret_cast<const uint4*>(in_hi + go) : z;
        *reinterpret_cast<uint4*>(smem + A_LO + da) =
            ok ? *reinterpret_cast<const uint4*>(in_lo + go) : z;
    }

    float d[4][2][4];
#pragma unroll
    for (int mt = 0; mt < 4; mt++)
#pragma unroll
        for (int nt = 0; nt < 2; nt++)
#pragma unroll
            for (int j = 0; j < 4; j++) d[mt][nt][j] = 0.f;

    for (int tap = 0; tap < 9; tap++) {
        __syncthreads();   // protects B reuse (and first-iteration A staging)
        // stage B for this tap: [oc][ch] rows, hi & lo
        for (int i = tid; i < 64*8; i += 256) {
            const int oc = i >> 3, g = i & 7;
            const uint32_t da = oc*128 + ((g ^ (oc & 7)) << 4);
            const size_t so = ((size_t)(tap*64 + oc))*64 + g*8;
            *reinterpret_cast<uint4*>(smem + B_HI + da) =
                *reinterpret_cast<const uint4*>(w_hi + so);
            *reinterpret_cast<uint4*>(smem + B_LO + da) =
                *reinterpret_cast<const uint4*>(w_lo + so);
        }
        __syncthreads();

        const int dy = tap/3 - 1, dx = tap%3 - 1;
        const uint32_t rplane = (uint32_t)(dy+1)*AROWB;

#pragma unroll
        for (int term = 0; term < 3; term++) {
            const uint32_t Aofs = (term == 1) ? A_LO : A_HI;
            const uint32_t Bofs = (term == 2) ? B_LO : B_HI;
#pragma unroll
            for (int ks = 0; ks < 4; ks++) {
                uint32_t bfr[4];
                {
                    const int grp = lane >> 3, row = lane & 7;
                    const int oc = ocb + ((grp >> 1) << 3) + row;
                    const int g  = 2*ks + (grp & 1);
                    ldsm_x4(bfr, sb + Bofs + oc*128 + ((g ^ (oc & 7)) << 4));
                }
#pragma unroll
                for (int mt = 0; mt < 4; mt++) {
                    uint32_t afr[4];
                    const int grp = lane >> 3, row = lane & 7;
                    const int m = mbase + mt*16 + ((grp & 1) << 3) + row;
                    const int g = 2*ks + (grp >> 1);
                    const int px = m + dx + 1;
                    ldsm_x4(afr, sb + Aofs + rplane + px*128 + ((g ^ (px & 7)) << 4));
                    mma16816(d[mt][0], afr, bfr);
                    mma16816(d[mt][1], afr, bfr + 2);
                }
            }
        }
    }
    __syncthreads();

    // ---- epilogue -----------------------------------------------------------
    if (layer == 0) {
        // leaky relu -> bf16 hi/lo, [px][ch] layout (4B packed-pair stores)
#pragma unroll
        for (int mt = 0; mt < 4; mt++) {
#pragma unroll
            for (int nt = 0; nt < 2; nt++) {
#pragma unroll
                for (int half = 0; half < 2; half++) {
                    float v0 = d[mt][nt][2*half+0];
                    float v1 = d[mt][nt][2*half+1];
                    v0 = v0 > 0.f ? v0 : 0.1f*v0;
                    v1 = v1 > 0.f ? v1 : 0.1f*v1;
                    __nv_bfloat16 h0 = __float2bfloat16(v0);
                    __nv_bfloat16 h1 = __float2bfloat16(v1);
                    __nv_bfloat16 l0 = __float2bfloat16(v0 - __bfloat162float(h0));
                    __nv_bfloat16 l1 = __float2bfloat16(v1 - __bfloat162float(h1));
                    const int m  = mbase + mt*16 + (lane >> 2) + half*8;
                    const int c  = ocb + nt*8 + 2*(lane & 3);
                    const size_t o = (((size_t)(n*H_ + y))*W_ + x0 + m)*64 + c;
                    *reinterpret_cast<uint32_t*>(g_mid_hi + o) =
                        ((uint32_t)__bfloat16_as_ushort(h1) << 16) | __bfloat16_as_ushort(h0);
                    *reinterpret_cast<uint32_t*>(g_mid_lo + o) =
                        ((uint32_t)__bfloat16_as_ushort(l1) << 16) | __bfloat16_as_ushort(l0);
                }
            }
        }
    } else {
        // transpose via smem -> coalesced NCHW + residual
        float* sf = reinterpret_cast<float*>(smem);   // [64][132]
#pragma unroll
        for (int mt = 0; mt < 4; mt++) {
#pragma unroll
            for (int nt = 0; nt < 2; nt++) {
#pragma unroll
                for (int half = 0; half < 2; half++) {
                    const int m = mbase + mt*16 + (lane >> 2) + half*8;
                    const int c = ocb + nt*8 + 2*(lane & 3);
                    sf[(c+0)*APX + m] = d[mt][nt][2*half+0];
                    sf[(c+1)*APX + m] = d[mt][nt][2*half+1];
                }
            }
        }
        __syncthreads();
        const float* res = (n < 2) ? (xl + n*CHW) : (xr + (n-2)*CHW);
        float* ob = g_buf + (size_t)n*CHW;
        const int pix0 = y*W_ + x0;
        for (int i = tid; i < 64*128; i += 256) {
            const int c = i >> 7, px = i & 127;
            const size_t o = (size_t)c*HW + pix0 + px;
            ob[o] = sf[c*APX + px] + res[o];
        }
    }
}

// ---------------- 1x1 conv (64->64) : NCHW in -> [b][p][c] out, FFMA2 --------
__global__ __launch_bounds__(256, 2)
void gemm1x1_kernel(int in_off, const float* __restrict__ w,
                    const float* __restrict__ bias, int out_sel)
{
    __shared__ __align__(16) float wsm[64][64];
    __shared__ __align__(16) float bsm[64];
    for (int i = threadIdx.x; i < 4096; i += 256) {
        int ic = i >> 6, oc = i & 63;
        wsm[ic][oc] = w[oc*64 + ic];
    }
    if (threadIdx.x < 64) bsm[threadIdx.x] = bias[threadIdx.x];
    __syncthreads();

    const int pp = threadIdx.x & 127;
    const int oh = threadIdx.x >> 7;
    const int p0 = blockIdx.x*256 + 2*pp;
    const int img = p0 >> 15, p = p0 & (HW-1);
    const float* ip = g_buf + in_off + img*CHW + p;

    ull acc0[16], acc1[16];
#pragma unroll
    for (int pi = 0; pi < 16; pi++) {
        ull b = *reinterpret_cast<const ull*>(&bsm[oh*32 + 2*pi]);
        acc0[pi] = b; acc1[pi] = b;
    }
#pragma unroll 4
    for (int ic = 0; ic < 64; ic++) {
        float2 pv = *reinterpret_cast<const float2*>(&ip[(size_t)ic*HW]);
        ull s0 = splat2(pv.x), s1 = splat2(pv.y);
        const ulonglong2* wp = reinterpret_cast<const ulonglong2*>(&wsm[ic][oh*32]);
#pragma unroll
        for (int j = 0; j < 8; j++) {
            ulonglong2 wv = wp[j];
            FMA2(acc0[2*j+0], wv.x, s0);
            FMA2(acc0[2*j+1], wv.y, s0);
            FMA2(acc1[2*j+0], wv.x, s1);
            FMA2(acc1[2*j+1], wv.y, s1);
        }
    }
    float* ob = (out_sel == 0 ? g_Q : (out_sel == 1 ? g_S : g_R));
    ull* o0 = reinterpret_cast<ull*>(ob + (size_t)p0*64 + oh*32);
    ull* o1 = reinterpret_cast<ull*>(ob + (size_t)(p0+1)*64 + oh*32);
#pragma unroll
    for (int pi = 0; pi < 16; pi++) { o0[pi] = acc0[pi]; o1[pi] = acc1[pi]; }
}

// ---------------- attention: warp per pixel, K = 16 --------------------------
__global__ __launch_bounds__(256)
void attn_kernel(const int* __restrict__ xxs, const int* __restrict__ yys,
                 float* __restrict__ outM)
{
    const unsigned FULL = 0xffffffffu;
    const int warp = threadIdx.x >> 5, lane = threadIdx.x & 31;
    const int gp = blockIdx.x*8 + warp;
    const int b  = gp >> 15;

    const float2 q = reinterpret_cast<const float2*>(g_Q + (size_t)gp*64)[lane];

    int idx = 0;
    if (lane < 16) {
        int i = gp*16 + lane;
        idx = xxs[i]*W_ + yys[i];
    }
    const float* Sb = g_S + (size_t)b*HW*64;
    const float* Rb = g_R + (size_t)b*HW*64;

    float myscore = -1e30f;
#pragma unroll
    for (int k = 0; k < 16; k++) {
        int id = __shfl_sync(FULL, idx, k);
        float2 kv = reinterpret_cast<const float2*>(Sb + (size_t)id*64)[lane];
        float s = q.x*kv.x + q.y*kv.y;
#pragma unroll
        for (int off = 16; off; off >>= 1) s += __shfl_xor_sync(FULL, s, off);
        if (lane == k) myscore = s;
    }
    float mx = myscore;
#pragma unroll
    for (int off = 8; off; off >>= 1) mx = fmaxf(mx, __shfl_xor_sync(FULL, mx, off));
    float e = expf(myscore - mx);
    float sum = e;
#pragma unroll
    for (int off = 8; off; off >>= 1) sum += __shfl_xor_sync(FULL, sum, off);
    float m = e / sum;

    float2 accv = make_float2(0.f, 0.f);
#pragma unroll
    for (int k = 0; k < 16; k++) {
        float mk = __shfl_sync(FULL, m, k);
        int   id = __shfl_sync(FULL, idx, k);
        float2 vv = reinterpret_cast<const float2*>(Rb + (size_t)id*64)[lane];
        accv.x = fmaf(mk, vv.x, accv.x);
        accv.y = fmaf(mk, vv.y, accv.y);
    }
    reinterpret_cast<float2*>(g_attn + (size_t)gp*64)[lane] = accv;
    if (lane < 16) outM[(size_t)gp*16 + lane] = m;
}

// ---------------- fusion 1x1: [attn(64) ; x_left(64)] -> 64, FFMA2 -----------
__global__ __launch_bounds__(256)
void fuse_kernel(const float* __restrict__ xl, const float* __restrict__ fw,
                 const float* __restrict__ fb, float* __restrict__ out)
{
    __shared__ __align__(16) float tile[256][17];
    __shared__ __align__(16) float wsm[16][64];
    __shared__ __align__(16) float bsm[64];

    const int t = threadIdx.x;
    if (t < 64) bsm[t] = fb[t];

    const int pp = t & 127, oh = t >> 7;
    const int gp0 = blockIdx.x*256;
    const int p0  = gp0 + 2*pp;
    const int img = p0 >> 15, p = p0 & (HW-1);

    ull acc0[16], acc1[16];
#pragma unroll
    for (int i = 0; i < 16; i++) { acc0[i] = 0ull; acc1[i] = 0ull; }

    for (int c0 = 0; c0 < 64; c0 += 16) {
        __syncthreads();
        for (int i = t; i < 4096; i += 256) {
            int px = i >> 4, icl = i & 15;
            tile[px][icl] = g_attn[(size_t)(gp0+px)*64 + c0 + icl];
        }
        for (int i = t; i < 1024; i += 256) {
            int icl = i >> 6, oc = i & 63;
            wsm[icl][oc] = fw[oc*128 + c0 + icl];
        }
        __syncthreads();
#pragma unroll
        for (int icl = 0; icl < 16; icl++) {
            ull s0 = splat2(tile[2*pp][icl]);
            ull s1 = splat2(tile[2*pp+1][icl]);
            const ulonglong2* wp = reinterpret_cast<const ulonglong2*>(&wsm[icl][oh*32]);
#pragma unroll
            for (int j = 0; j < 8; j++) {
                ulonglong2 wv = wp[j];
                FMA2(acc0[2*j+0], wv.x, s0);
                FMA2(acc0[2*j+1], wv.y, s0);
                FMA2(acc1[2*j+0], wv.x, s1);
                FMA2(acc1[2*j+1], wv.y, s1);
            }
        }
    }

    const float* xb = xl + img*CHW + p;
    for (int c0 = 0; c0 < 64; c0 += 16) {
        __syncthreads();
        for (int i = t; i < 1024; i += 256) {
            int icl = i >> 6, oc = i & 63;
            wsm[icl][oc] = fw[oc*128 + 64 + c0 + icl];
        }
        __syncthreads();
#pragma unroll
        for (int icl = 0; icl < 16; icl++) {
            float2 xv = *reinterpret_cast<const float2*>(&xb[(size_t)(c0+icl)*HW]);
            ull s0 = splat2(xv.x);
            ull s1 = splat2(xv.y);
            const ulonglong2* wp = reinterpret_cast<const ulonglong2*>(&wsm[icl][oh*32]);
#pragma unroll
            for (int j = 0; j < 8; j++) {
                ulonglong2 wv = wp[j];
                FMA2(acc0[2*j+0], wv.x, s0);
                FMA2(acc0[2*j+1], wv.y, s0);
                FMA2(acc1[2*j+0], wv.x, s1);
                FMA2(acc1[2*j+1], wv.y, s1);
            }
        }
    }

    float* ob = out + img*CHW + p;
#pragma unroll
    for (int pi = 0; pi < 16; pi++) {
        float e0,o0,e1,o1;
        unpack2(e0,o0,acc0[pi]); unpack2(e1,o1,acc1[pi]);
        int oce = oh*32 + 2*pi;
        float be = bsm[oce], bo = bsm[oce+1];
        *reinterpret_cast<float2*>(&ob[(size_t)oce*HW])     = make_float2(e0+be, e1+be);
        *reinterpret_cast<float2*>(&ob[(size_t)(oce+1)*HW]) = make_float2(o0+bo, o1+bo);
    }
}

// -----------------------------------------------------------------------------
extern "C" void kernel_launch(void* const* d_in, const int* in_sizes, int n_in,
                              void* d_out, int out_size)
{
    const float* xl    = (const float*)d_in[0];
    const float* xr    = (const float*)d_in[1];
    const int*   xxs   = (const int*)  d_in[2];
    const int*   yys   = (const int*)  d_in[3];
    const float* rb_w1 = (const float*)d_in[5];
    const float* rb_w2 = (const float*)d_in[6];
    const float* b1_w  = (const float*)d_in[7];
    const float* b1_b  = (const float*)d_in[8];
    const float* b2_w  = (const float*)d_in[9];
    const float* b2_b  = (const float*)d_in[10];
    const float* b3_w  = (const float*)d_in[11];
    const float* b3_b  = (const float*)d_in[12];
    const float* fus_w = (const float*)d_in[13];
    const float* fus_b = (const float*)d_in[14];
    float* out = (float*)d_out;

    static int attr_set = 0;
    if (!attr_set) {
        cudaFuncSetAttribute(conv_mma_kernel,
                             cudaFuncAttributeMaxDynamicSharedMemorySize, SMEM_CONV);
        attr_set = 1;
    }

    // resolve device-global addresses for kernel args
    __nv_bfloat16 *p_in_hi, *p_in_lo, *p_mid_hi, *p_mid_lo;
    __nv_bfloat16 *p_w1h, *p_w1l, *p_w2h, *p_w2l;
    cudaGetSymbolAddress((void**)&p_in_hi,  g_in_hi);
    cudaGetSymbolAddress((void**)&p_in_lo,  g_in_lo);
    cudaGetSymbolAddress((void**)&p_mid_hi, g_mid_hi);
    cudaGetSymbolAddress((void**)&p_mid_lo, g_mid_lo);
    cudaGetSymbolAddress((void**)&p_w1h, g_w1_hi);
    cudaGetSymbolAddress((void**)&p_w1l, g_w1_lo);
    cudaGetSymbolAddress((void**)&p_w2h, g_w2_hi);
    cudaGetSymbolAddress((void**)&p_w2l, g_w2_lo);

    prep_kernel<<<512, 256>>>(xl, xr);
    prep_w_kernel<<<144, 256>>>(rb_w1, rb_w2);

    conv_mma_kernel<<<1024, 256, SMEM_CONV>>>(p_in_hi,  p_in_lo,  p_w1h, p_w1l, xl, xr, 0);
    conv_mma_kernel<<<1024, 256, SMEM_CONV>>>(p_mid_hi, p_mid_lo, p_w2h, p_w2l, xl, xr, 1);

    gemm1x1_kernel<<<256, 256>>>(0,     b1_w, b1_b, 0);
    gemm1x1_kernel<<<256, 256>>>(2*CHW, b2_w, b2_b, 1);
    gemm1x1_kernel<<<256, 256>>>(2*CHW, b3_w, b3_b, 2);

    attn_kernel<<<8192, 256>>>(xxs, yys, out + MOFF);
    fuse_kernel<<<256, 256>>>(xl, fus_w, fus_b, out);
}

// round 6
// speedup vs baseline: 2.4216x; 1.1929x over previous
#include <cuda_runtime.h>
#include <cuda_bf16.h>
#include <cstdint>

#define H_  128
#define W_  256
#define HW  32768
#define C_  64
#define CHW (C_*HW)          // 2,097,152
#define MOFF (2*CHW)         // out elements = 4,194,304

typedef unsigned long long ull;

// ---------------- packed f32x2 helpers (scalar-path kernels) -----------------
#define FMA2(d,a,b) asm("fma.rn.f32x2 %0, %1, %2, %0;" : "+l"(d) : "l"(a), "l"(b))
__device__ __forceinline__ ull splat2(float v) {
    ull r; asm("mov.b64 %0, {%1, %1};" : "=l"(r) : "f"(v)); return r;
}
__device__ __forceinline__ void unpack2(float& lo, float& hi, ull p) {
    asm("mov.b64 {%0, %1}, %2;" : "=f"(lo), "=f"(hi) : "l"(p));
}

// ---------------- mma.sync / ldmatrix helpers (baseline PTX, sm_80+) ---------
__device__ __forceinline__ uint32_t smem_u32(const void* p) {
    uint32_t a;
    asm("{ .reg .u64 t; cvta.to.shared.u64 t, %1; cvt.u32.u64 %0, t; }" : "=r"(a) : "l"(p));
    return a;
}
__device__ __forceinline__ void ldsm_x4(uint32_t* r, uint32_t addr) {
    asm volatile("ldmatrix.sync.aligned.m8n8.x4.shared.b16 {%0,%1,%2,%3}, [%4];"
        : "=r"(r[0]), "=r"(r[1]), "=r"(r[2]), "=r"(r[3]) : "r"(addr));
}
__device__ __forceinline__ void mma16816(float* d, const uint32_t* a, const uint32_t* b) {
    asm volatile("mma.sync.aligned.m16n8k16.row.col.f32.bf16.bf16.f32 "
        "{%0,%1,%2,%3}, {%4,%5,%6,%7}, {%8,%9}, {%0,%1,%2,%3};"
        : "+f"(d[0]), "+f"(d[1]), "+f"(d[2]), "+f"(d[3])
        : "r"(a[0]), "r"(a[1]), "r"(a[2]), "r"(a[3]), "r"(b[0]), "r"(b[1]));
}

// ---------------- scratch ----------------------------------------------------
__device__ __align__(16) __nv_bfloat16 g_in_hi [4*HW*C_];   // [img][y][x][ch]
__device__ __align__(16) __nv_bfloat16 g_in_lo [4*HW*C_];
__device__ __align__(16) __nv_bfloat16 g_mid_hi[4*HW*C_];
__device__ __align__(16) __nv_bfloat16 g_mid_lo[4*HW*C_];
__device__ __align__(16) __nv_bfloat16 g_w1_hi[9*64*64];    // [tap][oc][ch]
__device__ __align__(16) __nv_bfloat16 g_w1_lo[9*64*64];
__device__ __align__(16) __nv_bfloat16 g_w2_hi[9*64*64];
__device__ __align__(16) __nv_bfloat16 g_w2_lo[9*64*64];
__device__ __align__(16) float g_buf [4*CHW];               // NCHW
__device__ __align__(16) float g_Q   [2*HW*C_];             // [b][p][c]
__device__ __align__(16) float g_S   [2*HW*C_];
__device__ __align__(16) float g_R   [2*HW*C_];
__device__ __align__(16) float g_attn[2*HW*C_];

// ---------------- prep: fp32 NCHW -> bf16 hi/lo [img][y][x][ch] --------------
__global__ __launch_bounds__(256)
void prep_kernel(const float* __restrict__ xl, const float* __restrict__ xr)
{
    const int gp = blockIdx.x*256 + threadIdx.x;   // 0..4*HW-1
    const int n  = gp >> 15, pix = gp & (HW-1);
    const float* src = ((n < 2) ? (xl + n*CHW) : (xr + (n-2)*CHW)) + pix;

    uint32_t hb[32], lb[32];
#pragma unroll
    for (int j = 0; j < 32; j++) {
        float v0 = src[(size_t)(2*j)*HW];
        float v1 = src[(size_t)(2*j+1)*HW];
        __nv_bfloat16 h0 = __float2bfloat16(v0);
        __nv_bfloat16 h1 = __float2bfloat16(v1);
        __nv_bfloat16 l0 = __float2bfloat16(v0 - __bfloat162float(h0));
        __nv_bfloat16 l1 = __float2bfloat16(v1 - __bfloat162float(h1));
        hb[j] = ((uint32_t)__bfloat16_as_ushort(h1) << 16) | __bfloat16_as_ushort(h0);
        lb[j] = ((uint32_t)__bfloat16_as_ushort(l1) << 16) | __bfloat16_as_ushort(l0);
    }
    uint4* dh = reinterpret_cast<uint4*>(g_in_hi + (size_t)gp*64);
    uint4* dl = reinterpret_cast<uint4*>(g_in_lo + (size_t)gp*64);
    const uint4* sh = reinterpret_cast<const uint4*>(hb);
    const uint4* sl = reinterpret_cast<const uint4*>(lb);
#pragma unroll
    for (int j = 0; j < 8; j++) { dh[j] = sh[j]; dl[j] = sl[j]; }
}

// ---------------- prep weights: fp32 [oc][ci][tap] -> bf16 hi/lo [tap][oc][ci]
__global__ __launch_bounds__(256)
void prep_w_kernel(const float* __restrict__ w1, const float* __restrict__ w2)
{
    const int i = blockIdx.x*256 + threadIdx.x;    // 0..9*4096-1
    if (i >= 9*4096) return;
    const int tap = i >> 12, r = i & 4095;
    const int oc = r >> 6, ci = r & 63;
    const int src = (oc*64 + ci)*9 + tap;
    const int dst = (tap*64 + oc)*64 + ci;
    float v1 = w1[src], v2 = w2[src];
    __nv_bfloat16 h1 = __float2bfloat16(v1);
    __nv_bfloat16 h2 = __float2bfloat16(v2);
    g_w1_hi[dst] = h1;
    g_w1_lo[dst] = __float2bfloat16(v1 - __bfloat162float(h1));
    g_w2_hi[dst] = h2;
    g_w2_lo[dst] = __float2bfloat16(v2 - __bfloat162float(h2));
}

// ---------------- HMMA 3x3 conv ----------------------------------------------
// Tile: M=128 pixels (half row) x N=64 oc. 16 warps: 4(M) x 4(N).
// K = 9 taps x 64 ch, 3 split terms (Ah*Bh, Al*Bh, Ah*Bl).
// smem: A = 3 row-planes x 132 px x 128B (hi + lo), B double-buffered per tap.
#define APX   132
#define AROWB (APX*128)               // 16896 bytes per row-plane
#define A_HI  0u
#define A_LO  (3u*AROWB)              // 50688
#define B_OFF (6u*AROWB)              // 101376
#define SMEM_CONV (6u*AROWB + 32768u) // 134144

__global__ __launch_bounds__(512, 1)
void conv_mma_kernel(const __nv_bfloat16* __restrict__ in_hi,
                     const __nv_bfloat16* __restrict__ in_lo,
                     const __nv_bfloat16* __restrict__ w_hi,
                     const __nv_bfloat16* __restrict__ w_lo,
                     const float* __restrict__ xl, const float* __restrict__ xr,
                     int layer)
{
    extern __shared__ __align__(16) char smem[];
    const uint32_t sb = smem_u32(smem);
    const int tid = threadIdx.x;
    const int lane = tid & 31, warp = tid >> 5;
    const int wm = warp & 3, wn = warp >> 2;
    const int mbase = wm*32, ocb = wn*16;
    const int grp = lane >> 3, row = lane & 7;

    for (int tile = blockIdx.x; tile < 1024; tile += gridDim.x) {
        const int n  = tile >> 8;
        const int y  = (tile >> 1) & 127;
        const int x0 = (tile & 1) * 128;

        // ---- stage A: 3 rows x 130 px x 8 granules(16B), hi & lo, swizzled --
        for (int i = tid; i < 3*130*8; i += 512) {
            const int r = i / (130*8), rem = i % (130*8);
            const int px = rem >> 3, g = rem & 7;
            const int gy = y + r - 1, gx = x0 + px - 1;
            const bool ok = ((unsigned)gy < (unsigned)H_) && ((unsigned)gx < (unsigned)W_);
            const size_t go = (((size_t)(n*H_ + gy))*W_ + gx)*64 + g*8;
            const uint32_t da = r*AROWB + px*128 + ((g ^ (px & 7)) << 4);
            const uint4 z = make_uint4(0,0,0,0);
            *reinterpret_cast<uint4*>(smem + A_HI + da) =
                ok ? *reinterpret_cast<const uint4*>(in_hi + go) : z;
            *reinterpret_cast<uint4*>(smem + A_LO + da) =
                ok ? *reinterpret_cast<const uint4*>(in_lo + go) : z;
        }
        // ---- stage B tap 0 into buffer 0 ----
        for (int i = tid; i < 64*8; i += 512) {
            const int oc = i >> 3, g = i & 7;
            const uint32_t da = B_OFF + oc*128 + ((g ^ (oc & 7)) << 4);
            const size_t so = ((size_t)oc)*64 + g*8;
            *reinterpret_cast<uint4*>(smem + da)         = *reinterpret_cast<const uint4*>(w_hi + so);
            *reinterpret_cast<uint4*>(smem + da + 8192u) = *reinterpret_cast<const uint4*>(w_lo + so);
        }
        __syncthreads();

        float d[2][2][4];
#pragma unroll
        for (int mt = 0; mt < 2; mt++)
#pragma unroll
            for (int nt = 0; nt < 2; nt++)
#pragma unroll
                for (int j = 0; j < 4; j++) d[mt][nt][j] = 0.f;

        for (int tap = 0; tap < 9; tap++) {
            // prefetch next tap's B into the other buffer (overlaps compute)
            if (tap < 8) {
                const uint32_t bdst = B_OFF + ((tap+1) & 1)*16384u;
                for (int i = tid; i < 64*8; i += 512) {
                    const int oc = i >> 3, g = i & 7;
                    const uint32_t da = bdst + oc*128 + ((g ^ (oc & 7)) << 4);
                    const size_t so = ((size_t)((tap+1)*64 + oc))*64 + g*8;
                    *reinterpret_cast<uint4*>(smem + da) =
                        *reinterpret_cast<const uint4*>(w_hi + so);
                    *reinterpret_cast<uint4*>(smem + da + 8192u) =
                        *reinterpret_cast<const uint4*>(w_lo + so);
                }
            }

            const int dy = tap/3 - 1, dx = tap%3 - 1;
            const uint32_t rplane = (uint32_t)(dy+1)*AROWB;
            const uint32_t bcur = B_OFF + (tap & 1)*16384u;

            // cache B fragments for this tap (hi & lo, 4 k-steps)
            uint32_t Bh[4][4], Bl[4][4];
            {
                const int oc = ocb + ((grp >> 1) << 3) + row;
                const uint32_t brow = oc*128u;
#pragma unroll
                for (int ks = 0; ks < 4; ks++) {
                    const int g = 2*ks + (grp & 1);
                    const uint32_t a = brow + ((g ^ (oc & 7)) << 4);
                    ldsm_x4(Bh[ks], sb + bcur + a);
                    ldsm_x4(Bl[ks], sb + bcur + 8192u + a);
                }
            }
#pragma unroll
            for (int ks = 0; ks < 4; ks++) {
#pragma unroll
                for (int mt = 0; mt < 2; mt++) {
                    const int m = mbase + mt*16 + ((grp & 1) << 3) + row;
                    const int g = 2*ks + (grp >> 1);
                    const int px = m + dx + 1;
                    const uint32_t aoff = rplane + px*128u + ((g ^ (px & 7)) << 4);
                    uint32_t Ah[4], Al[4];
                    ldsm_x4(Ah, sb + A_HI + aoff);
                    ldsm_x4(Al, sb + A_LO + aoff);
                    mma16816(d[mt][0], Ah, Bh[ks]);
                    mma16816(d[mt][1], Ah, Bh[ks] + 2);
                    mma16816(d[mt][0], Al, Bh[ks]);
                    mma16816(d[mt][1], Al, Bh[ks] + 2);
                    mma16816(d[mt][0], Ah, Bl[ks]);
                    mma16816(d[mt][1], Ah, Bl[ks] + 2);
                }
            }
            __syncthreads();
        }

        // ---- epilogue -------------------------------------------------------
        if (layer == 0) {
#pragma unroll
            for (int mt = 0; mt < 2; mt++) {
#pragma unroll
                for (int nt = 0; nt < 2; nt++) {
#pragma unroll
                    for (int half = 0; half < 2; half++) {
                        float v0 = d[mt][nt][2*half+0];
                        float v1 = d[mt][nt][2*half+1];
                        v0 = v0 > 0.f ? v0 : 0.1f*v0;
                        v1 = v1 > 0.f ? v1 : 0.1f*v1;
                        __nv_bfloat16 h0 = __float2bfloat16(v0);
                        __nv_bfloat16 h1 = __float2bfloat16(v1);
                        __nv_bfloat16 l0 = __float2bfloat16(v0 - __bfloat162float(h0));
                        __nv_bfloat16 l1 = __float2bfloat16(v1 - __bfloat162float(h1));
                        const int m  = mbase + mt*16 + (lane >> 2) + half*8;
                        const int c  = ocb + nt*8 + 2*(lane & 3);
                        const size_t o = (((size_t)(n*H_ + y))*W_ + x0 + m)*64 + c;
                        *reinterpret_cast<uint32_t*>(g_mid_hi + o) =
                            ((uint32_t)__bfloat16_as_ushort(h1) << 16) | __bfloat16_as_ushort(h0);
                        *reinterpret_cast<uint32_t*>(g_mid_lo + o) =
                            ((uint32_t)__bfloat16_as_ushort(l1) << 16) | __bfloat16_as_ushort(l0);
                    }
                }
            }
        } else {
            // transpose via smem -> coalesced NCHW + residual
            float* sf = reinterpret_cast<float*>(smem);   // [64][APX]
#pragma unroll
            for (int mt = 0; mt < 2; mt++) {
#pragma unroll
                for (int nt = 0; nt < 2; nt++) {
#pragma unroll
                    for (int half = 0; half < 2; half++) {
                        const int m = mbase + mt*16 + (lane >> 2) + half*8;
                        const int c = ocb + nt*8 + 2*(lane & 3);
                        sf[(c+0)*APX + m] = d[mt][nt][2*half+0];
                        sf[(c+1)*APX + m] = d[mt][nt][2*half+1];
                    }
                }
            }
            __syncthreads();
            const float* res = (n < 2) ? (xl + n*CHW) : (xr + (n-2)*CHW);
            float* ob = g_buf + (size_t)n*CHW;
            const int pix0 = y*W_ + x0;
            for (int i = tid; i < 64*128; i += 512) {
                const int c = i >> 7, px = i & 127;
                const size_t o = (size_t)c*HW + pix0 + px;
                ob[o] = sf[c*APX + px] + res[o];
            }
        }
        __syncthreads();
    }
}

// ---------------- 1x1 conv (64->64) : NCHW in -> [b][p][c] out, FFMA2 --------
__global__ __launch_bounds__(256, 2)
void gemm1x1_kernel(int in_off, const float* __restrict__ w,
                    const float* __restrict__ bias, int out_sel)
{
    __shared__ __align__(16) float wsm[64][64];
    __shared__ __align__(16) float bsm[64];
    for (int i = threadIdx.x; i < 4096; i += 256) {
        int ic = i >> 6, oc = i & 63;
        wsm[ic][oc] = w[oc*64 + ic];
    }
    if (threadIdx.x < 64) bsm[threadIdx.x] = bias[threadIdx.x];
    __syncthreads();

    const int pp = threadIdx.x & 127;
    const int oh = threadIdx.x >> 7;
    const int p0 = blockIdx.x*256 + 2*pp;
    const int img = p0 >> 15, p = p0 & (HW-1);
    const float* ip = g_buf + in_off + img*CHW + p;

    ull acc0[16], acc1[16];
#pragma unroll
    for (int pi = 0; pi < 16; pi++) {
        ull b = *reinterpret_cast<const ull*>(&bsm[oh*32 + 2*pi]);
        acc0[pi] = b; acc1[pi] = b;
    }
#pragma unroll 4
    for (int ic = 0; ic < 64; ic++) {
        float2 pv = *reinterpret_cast<const float2*>(&ip[(size_t)ic*HW]);
        ull s0 = splat2(pv.x), s1 = splat2(pv.y);
        const ulonglong2* wp = reinterpret_cast<const ulonglong2*>(&wsm[ic][oh*32]);
#pragma unroll
        for (int j = 0; j < 8; j++) {
            ulonglong2 wv = wp[j];
            FMA2(acc0[2*j+0], wv.x, s0);
            FMA2(acc0[2*j+1], wv.y, s0);
            FMA2(acc1[2*j+0], wv.x, s1);
            FMA2(acc1[2*j+1], wv.y, s1);
        }
    }
    float* ob = (out_sel == 0 ? g_Q : (out_sel == 1 ? g_S : g_R));
    ull* o0 = reinterpret_cast<ull*>(ob + (size_t)p0*64 + oh*32);
    ull* o1 = reinterpret_cast<ull*>(ob + (size_t)(p0+1)*64 + oh*32);
#pragma unroll
    for (int pi = 0; pi < 16; pi++) { o0[pi] = acc0[pi]; o1[pi] = acc1[pi]; }
}

// ---------------- attention: warp per pixel, K = 16 --------------------------
__global__ __launch_bounds__(256)
void attn_kernel(const int* __restrict__ xxs, const int* __restrict__ yys,
                 float* __restrict__ outM)
{
    const unsigned FULL = 0xffffffffu;
    const int warp = threadIdx.x >> 5, lane = threadIdx.x & 31;
    const int gp = blockIdx.x*8 + warp;
    const int b  = gp >> 15;

    const float2 q = reinterpret_cast<const float2*>(g_Q + (size_t)gp*64)[lane];

    int idx = 0;
    if (lane < 16) {
        int i = gp*16 + lane;
        idx = xxs[i]*W_ + yys[i];
    }
    const float* Sb = g_S + (size_t)b*HW*64;
    const float* Rb = g_R + (size_t)b*HW*64;

    float myscore = -1e30f;
#pragma unroll
    for (int k = 0; k < 16; k++) {
        int id = __shfl_sync(FULL, idx, k);
        float2 kv = reinterpret_cast<const float2*>(Sb + (size_t)id*64)[lane];
        float s = q.x*kv.x + q.y*kv.y;
#pragma unroll
        for (int off = 16; off; off >>= 1) s += __shfl_xor_sync(FULL, s, off);
        if (lane == k) myscore = s;
    }
    float mx = myscore;
#pragma unroll
    for (int off = 8; off; off >>= 1) mx = fmaxf(mx, __shfl_xor_sync(FULL, mx, off));
    float e = expf(myscore - mx);
    float sum = e;
#pragma unroll
    for (int off = 8; off; off >>= 1) sum += __shfl_xor_sync(FULL, sum, off);
    float m = e / sum;

    float2 accv = make_float2(0.f, 0.f);
#pragma unroll
    for (int k = 0; k < 16; k++) {
        float mk = __shfl_sync(FULL, m, k);
        int   id = __shfl_sync(FULL, idx, k);
        float2 vv = reinterpret_cast<const float2*>(Rb + (size_t)id*64)[lane];
        accv.x = fmaf(mk, vv.x, accv.x);
        accv.y = fmaf(mk, vv.y, accv.y);
    }
    reinterpret_cast<float2*>(g_attn + (size_t)gp*64)[lane] = accv;
    if (lane < 16) outM[(size_t)gp*16 + lane] = m;
}

// ---------------- fusion 1x1: [attn(64) ; x_left(64)] -> 64, FFMA2 -----------
__global__ __launch_bounds__(256)
void fuse_kernel(const float* __restrict__ xl, const float* __restrict__ fw,
                 const float* __restrict__ fb, float* __restrict__ out)
{
    __shared__ __align__(16) float tile[256][17];
    __shared__ __align__(16) float wsm[16][64];
    __shared__ __align__(16) float bsm[64];

    const int t = threadIdx.x;
    if (t < 64) bsm[t] = fb[t];

    const int pp = t & 127, oh = t >> 7;
    const int gp0 = blockIdx.x*256;
    const int p0  = gp0 + 2*pp;
    const int img = p0 >> 15, p = p0 & (HW-1);

    ull acc0[16], acc1[16];
#pragma unroll
    for (int i = 0; i < 16; i++) { acc0[i] = 0ull; acc1[i] = 0ull; }

    for (int c0 = 0; c0 < 64; c0 += 16) {
        __syncthreads();
        for (int i = t; i < 4096; i += 256) {
            int px = i >> 4, icl = i & 15;
            tile[px][icl] = g_attn[(size_t)(gp0+px)*64 + c0 + icl];
        }
        for (int i = t; i < 1024; i += 256) {
            int icl = i >> 6, oc = i & 63;
            wsm[icl][oc] = fw[oc*128 + c0 + icl];
        }
        __syncthreads();
#pragma unroll
        for (int icl = 0; icl < 16; icl++) {
            ull s0 = splat2(tile[2*pp][icl]);
            ull s1 = splat2(tile[2*pp+1][icl]);
            const ulonglong2* wp = reinterpret_cast<const ulonglong2*>(&wsm[icl][oh*32]);
#pragma unroll
            for (int j = 0; j < 8; j++) {
                ulonglong2 wv = wp[j];
                FMA2(acc0[2*j+0], wv.x, s0);
                FMA2(acc0[2*j+1], wv.y, s0);
                FMA2(acc1[2*j+0], wv.x, s1);
                FMA2(acc1[2*j+1], wv.y, s1);
            }
        }
    }

    const float* xb = xl + img*CHW + p;
    for (int c0 = 0; c0 < 64; c0 += 16) {
        __syncthreads();
        for (int i = t; i < 1024; i += 256) {
            int icl = i >> 6, oc = i & 63;
            wsm[icl][oc] = fw[oc*128 + 64 + c0 + icl];
        }
        __syncthreads();
#pragma unroll
        for (int icl = 0; icl < 16; icl++) {
            float2 xv = *reinterpret_cast<const float2*>(&xb[(size_t)(c0+icl)*HW]);
            ull s0 = splat2(xv.x);
            ull s1 = splat2(xv.y);
            const ulonglong2* wp = reinterpret_cast<const ulonglong2*>(&wsm[icl][oh*32]);
#pragma unroll
            for (int j = 0; j < 8; j++) {
                ulonglong2 wv = wp[j];
                FMA2(acc0[2*j+0], wv.x, s0);
                FMA2(acc0[2*j+1], wv.y, s0);
                FMA2(acc1[2*j+0], wv.x, s1);
                FMA2(acc1[2*j+1], wv.y, s1);
            }
        }
    }

    float* ob = out + img*CHW + p;
#pragma unroll
    for (int pi = 0; pi < 16; pi++) {
        float e0,o0,e1,o1;
        unpack2(e0,o0,acc0[pi]); unpack2(e1,o1,acc1[pi]);
        int oce = oh*32 + 2*pi;
        float be = bsm[oce], bo = bsm[oce+1];
        *reinterpret_cast<float2*>(&ob[(size_t)oce*HW])     = make_float2(e0+be, e1+be);
        *reinterpret_cast<float2*>(&ob[(size_t)(oce+1)*HW]) = make_float2(o0+bo, o1+bo);
    }
}

// -----------------------------------------------------------------------------
extern "C" void kernel_launch(void* const* d_in, const int* in_sizes, int n_in,
                              void* d_out, int out_size)
{
    const float* xl    = (const float*)d_in[0];
    const float* xr    = (const float*)d_in[1];
    const int*   xxs   = (const int*)  d_in[2];
    const int*   yys   = (const int*)  d_in[3];
    const float* rb_w1 = (const float*)d_in[5];
    const float* rb_w2 = (const float*)d_in[6];
    const float* b1_w  = (const float*)d_in[7];
    const float* b1_b  = (const float*)d_in[8];
    const float* b2_w  = (const float*)d_in[9];
    const float* b2_b  = (const float*)d_in[10];
    const float* b3_w  = (const float*)d_in[11];
    const float* b3_b  = (const float*)d_in[12];
    const float* fus_w = (const float*)d_in[13];
    const float* fus_b = (const float*)d_in[14];
    float* out = (float*)d_out;

    static int attr_set = 0;
    if (!attr_set) {
        cudaFuncSetAttribute(conv_mma_kernel,
                             cudaFuncAttributeMaxDynamicSharedMemorySize, SMEM_CONV);
        attr_set = 1;
    }

    __nv_bfloat16 *p_in_hi, *p_in_lo, *p_mid_hi, *p_mid_lo;
    __nv_bfloat16 *p_w1h, *p_w1l, *p_w2h, *p_w2l;
    cudaGetSymbolAddress((void**)&p_in_hi,  g_in_hi);
    cudaGetSymbolAddress((void**)&p_in_lo,  g_in_lo);
    cudaGetSymbolAddress((void**)&p_mid_hi, g_mid_hi);
    cudaGetSymbolAddress((void**)&p_mid_lo, g_mid_lo);
    cudaGetSymbolAddress((void**)&p_w1h, g_w1_hi);
    cudaGetSymbolAddress((void**)&p_w1l, g_w1_lo);
    cudaGetSymbolAddress((void**)&p_w2h, g_w2_hi);
    cudaGetSymbolAddress((void**)&p_w2l, g_w2_lo);

    prep_kernel<<<512, 256>>>(xl, xr);
    prep_w_kernel<<<144, 256>>>(rb_w1, rb_w2);

    conv_mma_kernel<<<148, 512, SMEM_CONV>>>(p_in_hi,  p_in_lo,  p_w1h, p_w1l, xl, xr, 0);
    conv_mma_kernel<<<148, 512, SMEM_CONV>>>(p_mid_hi, p_mid_lo, p_w2h, p_w2l, xl, xr, 1);

    gemm1x1_kernel<<<256, 256>>>(0,     b1_w, b1_b, 0);
    gemm1x1_kernel<<<256, 256>>>(2*CHW, b2_w, b2_b, 1);
    gemm1x1_kernel<<<256, 256>>>(2*CHW, b3_w, b3_b, 2);

    attn_kernel<<<8192, 256>>>(xxs, yys, out + MOFF);
    fuse_kernel<<<256, 256>>>(xl, fus_w, fus_b, out);
}

// round 8
// speedup vs baseline: 2.8683x; 1.1845x over previous
#include <cuda_runtime.h>
#include <cuda_bf16.h>
#include <cstdint>

#define H_  128
#define W_  256
#define HW  32768
#define C_  64
#define CHW (C_*HW)          // 2,097,152
#define MOFF (2*CHW)         // out elements = 4,194,304

typedef unsigned long long ull;

// ---------------- mma.sync / ldmatrix helpers (baseline PTX, sm_80+) ---------
__device__ __forceinline__ uint32_t smem_u32(const void* p) {
    uint32_t a;
    asm("{ .reg .u64 t; cvta.to.shared.u64 t, %1; cvt.u32.u64 %0, t; }" : "=r"(a) : "l"(p));
    return a;
}
__device__ __forceinline__ void ldsm_x4(uint32_t* r, uint32_t addr) {
    asm volatile("ldmatrix.sync.aligned.m8n8.x4.shared.b16 {%0,%1,%2,%3}, [%4];"
        : "=r"(r[0]), "=r"(r[1]), "=r"(r[2]), "=r"(r[3]) : "r"(addr));
}
__device__ __forceinline__ void mma16816(float* d, const uint32_t* a, const uint32_t* b) {
    asm volatile("mma.sync.aligned.m16n8k16.row.col.f32.bf16.bf16.f32 "
        "{%0,%1,%2,%3}, {%4,%5,%6,%7}, {%8,%9}, {%0,%1,%2,%3};"
        : "+f"(d[0]), "+f"(d[1]), "+f"(d[2]), "+f"(d[3])
        : "r"(a[0]), "r"(a[1]), "r"(a[2]), "r"(a[3]), "r"(b[0]), "r"(b[1]));
}
__device__ __forceinline__ uint32_t pack_hi(float v0, float v1, float& r0, float& r1) {
    __nv_bfloat16 h0 = __float2bfloat16(v0);
    __nv_bfloat16 h1 = __float2bfloat16(v1);
    r0 = v0 - __bfloat162float(h0);
    r1 = v1 - __bfloat162float(h1);
    return ((uint32_t)__bfloat16_as_ushort(h1) << 16) | __bfloat16_as_ushort(h0);
}
__device__ __forceinline__ uint32_t pack_lo(float r0, float r1) {
    return ((uint32_t)__bfloat16_as_ushort(__float2bfloat16(r1)) << 16)
         | __bfloat16_as_ushort(__float2bfloat16(r0));
}

// ---------------- scratch ----------------------------------------------------
__device__ __align__(16) __nv_bfloat16 g_in_hi [4*HW*C_];   // [img][y][x][ch]
__device__ __align__(16) __nv_bfloat16 g_in_lo [4*HW*C_];
__device__ __align__(16) __nv_bfloat16 g_mid_hi[4*HW*C_];
__device__ __align__(16) __nv_bfloat16 g_mid_lo[4*HW*C_];
__device__ __align__(16) __nv_bfloat16 g_buf_hi[4*HW*C_];   // residual block out
__device__ __align__(16) __nv_bfloat16 g_buf_lo[4*HW*C_];
__device__ __align__(16) __nv_bfloat16 g_att_hi[2*HW*C_];
__device__ __align__(16) __nv_bfloat16 g_att_lo[2*HW*C_];
__device__ __align__(16) __nv_bfloat16 g_w1_hi[9*64*64];    // [tap][oc][ch]
__device__ __align__(16) __nv_bfloat16 g_w1_lo[9*64*64];
__device__ __align__(16) __nv_bfloat16 g_w2_hi[9*64*64];
__device__ __align__(16) __nv_bfloat16 g_w2_lo[9*64*64];
__device__ __align__(16) __nv_bfloat16 g_wq_hi [64*64];     // [oc][ic]
__device__ __align__(16) __nv_bfloat16 g_wq_lo [64*64];
__device__ __align__(16) __nv_bfloat16 g_wsr_hi[128*64];    // S then R
__device__ __align__(16) __nv_bfloat16 g_wsr_lo[128*64];
__device__ __align__(16) __nv_bfloat16 g_wf_hi [64*128];    // fuse [oc][ic]
__device__ __align__(16) __nv_bfloat16 g_wf_lo [64*128];
__device__ __align__(16) float g_Q[2*HW*C_];                // [p][c] fp32
__device__ __align__(16) float g_S[2*HW*C_];
__device__ __align__(16) float g_R[2*HW*C_];

// ---------------- prep: fp32 NCHW -> bf16 hi/lo [img][y][x][ch] --------------
__global__ __launch_bounds__(256)
void prep_kernel(const float* __restrict__ xl, const float* __restrict__ xr)
{
    const int gp = blockIdx.x*256 + threadIdx.x;   // 0..4*HW-1
    const int n  = gp >> 15, pix = gp & (HW-1);
    const float* src = ((n < 2) ? (xl + n*CHW) : (xr + (n-2)*CHW)) + pix;

    uint32_t hb[32], lb[32];
#pragma unroll
    for (int j = 0; j < 32; j++) {
        float v0 = src[(size_t)(2*j)*HW];
        float v1 = src[(size_t)(2*j+1)*HW];
        float r0, r1;
        hb[j] = pack_hi(v0, v1, r0, r1);
        lb[j] = pack_lo(r0, r1);
    }
    uint4* dh = reinterpret_cast<uint4*>(g_in_hi + (size_t)gp*64);
    uint4* dl = reinterpret_cast<uint4*>(g_in_lo + (size_t)gp*64);
    const uint4* sh = reinterpret_cast<const uint4*>(hb);
    const uint4* sl = reinterpret_cast<const uint4*>(lb);
#pragma unroll
    for (int j = 0; j < 8; j++) { dh[j] = sh[j]; dl[j] = sl[j]; }
}

// ---------------- prep conv weights: [oc][ci][tap] -> hi/lo [tap][oc][ci] ----
__global__ __launch_bounds__(256)
void prep_w_kernel(const float* __restrict__ w1, const float* __restrict__ w2)
{
    const int i = blockIdx.x*256 + threadIdx.x;
    if (i >= 9*4096) return;
    const int tap = i >> 12, r = i & 4095;
    const int oc = r >> 6, ci = r & 63;
    const int src = (oc*64 + ci)*9 + tap;
    const int dst = (tap*64 + oc)*64 + ci;
    float v1 = w1[src], v2 = w2[src];
    __nv_bfloat16 h1 = __float2bfloat16(v1);
    __nv_bfloat16 h2 = __float2bfloat16(v2);
    g_w1_hi[dst] = h1;
    g_w1_lo[dst] = __float2bfloat16(v1 - __bfloat162float(h1));
    g_w2_hi[dst] = h2;
    g_w2_lo[dst] = __float2bfloat16(v2 - __bfloat162float(h2));
}

// ---------------- prep 1x1 weights (Q, S, R, fuse) ---------------------------
__global__ __launch_bounds__(256)
void prep_w2_kernel(const float* __restrict__ qw, const float* __restrict__ sw,
                    const float* __restrict__ rw, const float* __restrict__ fw)
{
    const int i = blockIdx.x*256 + threadIdx.x;
    if (i >= 20480) return;
    float v; __nv_bfloat16* dh; __nv_bfloat16* dl; int j;
    if (i < 4096)       { j = i;         v = qw[j]; dh = g_wq_hi  + j;      dl = g_wq_lo  + j; }
    else if (i < 8192)  { j = i - 4096;  v = sw[j]; dh = g_wsr_hi + j;      dl = g_wsr_lo + j; }
    else if (i < 12288) { j = i - 8192;  v = rw[j]; dh = g_wsr_hi + 4096+j; dl = g_wsr_lo + 4096+j; }
    else                { j = i - 12288; v = fw[j]; dh = g_wf_hi  + j;      dl = g_wf_lo  + j; }
    __nv_bfloat16 h = __float2bfloat16(v);
    *dh = h;
    *dl = __float2bfloat16(v - __bfloat162float(h));
}

// ---------------- HMMA 3x3 conv ----------------------------------------------
// Tile: M=64 px x N=64 oc. 8 warps: 4(M) x 2(N); warp = 16px x 32oc.
#define APX2  66
#define AROW2 (APX2*128)              // 8448
#define CA_HI 0u
#define CA_LO (3u*AROW2)              // 25344
#define CB_OFF (6u*AROW2)             // 50688
#define SMEM_CONV (CB_OFF + 32768u)   // 83456

__global__ __launch_bounds__(256, 2)
void conv_mma_kernel(const __nv_bfloat16* __restrict__ in_hi,
                     const __nv_bfloat16* __restrict__ in_lo,
                     const __nv_bfloat16* __restrict__ w_hi,
                     const __nv_bfloat16* __restrict__ w_lo,
                     const float* __restrict__ xl, const float* __restrict__ xr,
                     int layer)
{
    extern __shared__ __align__(16) char smem[];
    const uint32_t sb = smem_u32(smem);
    const int tid = threadIdx.x;
    const int lane = tid & 31, warp = tid >> 5;
    const int wm = warp & 3, wn = warp >> 2;
    const int mbase = wm*16, ocb = wn*32;
    const int grp = lane >> 3, row = lane & 7;

    for (int tile = blockIdx.x; tile < 2048; tile += gridDim.x) {
        const int n  = tile >> 9;
        const int y  = (tile >> 2) & 127;
        const int x0 = (tile & 3) * 64;

        // ---- stage A: 3 rows x 66 px x 8 granules, hi & lo -------------------
        for (int i = tid; i < 3*66*8; i += 256) {
            const int r = i / 528, rem = i % 528;
            const int px = rem >> 3, g = rem & 7;
            const int gy = y + r - 1, gx = x0 + px - 1;
            const bool ok = ((unsigned)gy < (unsigned)H_) && ((unsigned)gx < (unsigned)W_);
            const size_t go = (((size_t)(n*H_ + gy))*W_ + gx)*64 + g*8;
            const uint32_t da = r*AROW2 + px*128 + ((g ^ (px & 7)) << 4);
            const uint4 z = make_uint4(0,0,0,0);
            *reinterpret_cast<uint4*>(smem + CA_HI + da) =
                ok ? *reinterpret_cast<const uint4*>(in_hi + go) : z;
            *reinterpret_cast<uint4*>(smem + CA_LO + da) =
                ok ? *reinterpret_cast<const uint4*>(in_lo + go) : z;
        }
        // ---- stage B tap 0 into buffer 0 ----
        for (int i = tid; i < 512; i += 256) {
            const int oc = i >> 3, g = i & 7;
            const uint32_t da = CB_OFF + oc*128 + ((g ^ (oc & 7)) << 4);
            const size_t so = (size_t)oc*64 + g*8;
            *reinterpret_cast<uint4*>(smem + da)         = *reinterpret_cast<const uint4*>(w_hi + so);
            *reinterpret_cast<uint4*>(smem + da + 8192u) = *reinterpret_cast<const uint4*>(w_lo + so);
        }
        __syncthreads();

        float d[4][4];
#pragma unroll
        for (int f = 0; f < 4; f++)
#pragma unroll
            for (int j = 0; j < 4; j++) d[f][j] = 0.f;

        for (int tap = 0; tap < 9; tap++) {
            if (tap < 8) {
                const uint32_t bdst = CB_OFF + ((tap+1) & 1)*16384u;
                for (int i = tid; i < 512; i += 256) {
                    const int oc = i >> 3, g = i & 7;
                    const uint32_t da = bdst + oc*128 + ((g ^ (oc & 7)) << 4);
                    const size_t so = ((size_t)((tap+1)*64 + oc))*64 + g*8;
                    *reinterpret_cast<uint4*>(smem + da) =
                        *reinterpret_cast<const uint4*>(w_hi + so);
                    *reinterpret_cast<uint4*>(smem + da + 8192u) =
                        *reinterpret_cast<const uint4*>(w_lo + so);
                }
            }
            const int dy = tap/3 - 1, dx = tap%3 - 1;
            const uint32_t rplane = (uint32_t)(dy+1)*AROW2;
            const uint32_t bcur = CB_OFF + (tap & 1)*16384u;

#pragma unroll
            for (int ks = 0; ks < 4; ks++) {
                uint32_t Bh[8], Bl[8];
                {
                    const int oc0 = ocb + ((grp >> 1) << 3) + row;
                    const int g   = 2*ks + (grp & 1);
                    const uint32_t a0 = oc0*128u + ((g ^ (oc0 & 7)) << 4);
                    ldsm_x4(Bh,     sb + bcur + a0);
                    ldsm_x4(Bl,     sb + bcur + 8192u + a0);
                    const int oc1 = oc0 + 16;
                    const uint32_t a1 = oc1*128u + ((g ^ (oc1 & 7)) << 4);
                    ldsm_x4(Bh + 4, sb + bcur + a1);
                    ldsm_x4(Bl + 4, sb + bcur + 8192u + a1);
                }
                const int m  = mbase + ((grp & 1) << 3) + row;
                const int g  = 2*ks + (grp >> 1);
                const int px = m + dx + 1;
                const uint32_t aoff = rplane + px*128u + ((g ^ (px & 7)) << 4);
                uint32_t Ah[4], Al[4];
                ldsm_x4(Ah, sb + CA_HI + aoff);
                ldsm_x4(Al, sb + CA_LO + aoff);
#pragma unroll
                for (int f = 0; f < 4; f++) {
                    mma16816(d[f], Ah, Bh + 2*f);
                    mma16816(d[f], Al, Bh + 2*f);
                    mma16816(d[f], Ah, Bl + 2*f);
                }
            }
            __syncthreads();
        }

        // ---- epilogue -------------------------------------------------------
        const int mrow = (lane >> 2);
        const int cpair = 2*(lane & 3);
        if (layer == 0) {
#pragma unroll
            for (int f = 0; f < 4; f++) {
#pragma unroll
                for (int half = 0; half < 2; half++) {
                    float v0 = d[f][2*half+0], v1 = d[f][2*half+1];
                    v0 = v0 > 0.f ? v0 : 0.1f*v0;
                    v1 = v1 > 0.f ? v1 : 0.1f*v1;
                    const int m = mbase + mrow + half*8;
                    const int c = ocb + f*8 + cpair;
                    const size_t o = (((size_t)(n*H_ + y))*W_ + x0 + m)*64 + c;
                    float r0, r1;
                    *reinterpret_cast<uint32_t*>(g_mid_hi + o) = pack_hi(v0, v1, r0, r1);
                    *reinterpret_cast<uint32_t*>(g_mid_lo + o) = pack_lo(r0, r1);
                }
            }
        } else {
            const float* res = (n < 2) ? (xl + n*CHW) : (xr + (n-2)*CHW);
#pragma unroll
            for (int f = 0; f < 4; f++) {
#pragma unroll
                for (int half = 0; half < 2; half++) {
                    const int m = mbase + mrow + half*8;
                    const int c = ocb + f*8 + cpair;
                    const int pix = y*W_ + x0 + m;
                    float v0 = d[f][2*half+0] + res[(size_t)c*HW + pix];
                    float v1 = d[f][2*half+1] + res[(size_t)(c+1)*HW + pix];
                    const size_t o = ((size_t)n*HW + pix)*64 + c;
                    float r0, r1;
                    *reinterpret_cast<uint32_t*>(g_buf_hi + o) = pack_hi(v0, v1, r0, r1);
                    *reinterpret_cast<uint32_t*>(g_buf_lo + o) = pack_lo(r0, r1);
                }
            }
        }
        __syncthreads();
    }
}

// ---------------- generic HMMA GEMM: [65536 px] x NOC oc, K=64 ---------------
// 16 warps: 4(M) x 4(N); warp = 32px x NOC/4 oc. out fp32 [p][64] (split at 64).
#define QA_HI 0u
#define QA_LO 16384u
#define QB_HI 32768u
#define QB_LO (32768u + 16384u)
#define SMEM_GEMM 65536u

template<int NOC>
__global__ __launch_bounds__(512, 2)
void gemm_hmma(const __nv_bfloat16* __restrict__ a_hi,
               const __nv_bfloat16* __restrict__ a_lo,
               const __nv_bfloat16* __restrict__ w_hi,
               const __nv_bfloat16* __restrict__ w_lo,
               const float* __restrict__ biasA, const float* __restrict__ biasB,
               float* __restrict__ outA, float* __restrict__ outB)
{
    extern __shared__ __align__(16) char smem[];
    const uint32_t sb = smem_u32(smem);
    const int tid = threadIdx.x;
    const int lane = tid & 31, warp = tid >> 5;
    const int wm = warp & 3, wn = warp >> 2;
    constexpr int NW  = NOC/4;          // oc span per warp (16 or 32)
    constexpr int L16 = NW/16;          // 16-oc ldsm groups (1 or 2)
    constexpr int F8  = NW/8;           // 8-oc mma frags (2 or 4)
    const int mbase = wm*32, ocb = wn*NW;
    const int grp = lane >> 3, row = lane & 7;
    const int p0 = blockIdx.x * 128;

    for (int i = tid; i < 1024; i += 512) {
        const int px = i >> 3, g = i & 7;
        const uint32_t da = px*128 + ((g ^ (px & 7)) << 4);
        const size_t so = (size_t)(p0+px)*64 + g*8;
        *reinterpret_cast<uint4*>(smem + QA_HI + da) = *reinterpret_cast<const uint4*>(a_hi + so);
        *reinterpret_cast<uint4*>(smem + QA_LO + da) = *reinterpret_cast<const uint4*>(a_lo + so);
    }
    for (int i = tid; i < NOC*8; i += 512) {
        const int oc = i >> 3, g = i & 7;
        const uint32_t da = oc*128 + ((g ^ (oc & 7)) << 4);
        const size_t so = (size_t)oc*64 + g*8;
        *reinterpret_cast<uint4*>(smem + QB_HI + da) = *reinterpret_cast<const uint4*>(w_hi + so);
        *reinterpret_cast<uint4*>(smem + QB_LO + da) = *reinterpret_cast<const uint4*>(w_lo + so);
    }
    __syncthreads();

    float d[2][F8][4];
#pragma unroll
    for (int mt = 0; mt < 2; mt++)
#pragma unroll
        for (int f = 0; f < F8; f++)
#pragma unroll
            for (int j = 0; j < 4; j++) d[mt][f][j] = 0.f;

#pragma unroll
    for (int ks = 0; ks < 4; ks++) {
        uint32_t Bh[4*L16], Bl[4*L16];
#pragma unroll
        for (int l = 0; l < L16; l++) {
            const int oc = ocb + l*16 + ((grp >> 1) << 3) + row;
            const int g  = 2*ks + (grp & 1);
            const uint32_t a = oc*128u + ((g ^ (oc & 7)) << 4);
            ldsm_x4(Bh + 4*l, sb + QB_HI + a);
            ldsm_x4(Bl + 4*l, sb + QB_LO + a);
        }
#pragma unroll
        for (int mt = 0; mt < 2; mt++) {
            const int m = mbase + mt*16 + ((grp & 1) << 3) + row;
            const int g = 2*ks + (grp >> 1);
            const uint32_t a = m*128u + ((g ^ (m & 7)) << 4);
            uint32_t Ah[4], Al[4];
            ldsm_x4(Ah, sb + QA_HI + a);
            ldsm_x4(Al, sb + QA_LO + a);
#pragma unroll
            for (int f = 0; f < F8; f++) {
                mma16816(d[mt][f], Ah, Bh + 2*f);
                mma16816(d[mt][f], Al, Bh + 2*f);
                mma16816(d[mt][f], Ah, Bl + 2*f);
            }
        }
    }

#pragma unroll
    for (int mt = 0; mt < 2; mt++) {
#pragma unroll
        for (int f = 0; f < F8; f++) {
#pragma unroll
            for (int half = 0; half < 2; half++) {
                const int m = mbase + mt*16 + (lane >> 2) + half*8;
                const int c = ocb + f*8 + 2*(lane & 3);
                const float* bias = (c < 64) ? biasA : biasB;
                const int col = c & 63;
                float v0 = d[mt][f][2*half+0] + bias[col];
                float v1 = d[mt][f][2*half+1] + bias[col+1];
                float* o = ((c < 64) ? outA : outB) + (size_t)(p0+m)*64 + col;
                *reinterpret_cast<float2*>(o) = make_float2(v0, v1);
            }
        }
    }
}

// ---------------- attention: warp per pixel, K = 16 --------------------------
__global__ __launch_bounds__(256)
void attn_kernel(const int* __restrict__ xxs, const int* __restrict__ yys,
                 float* __restrict__ outM)
{
    const unsigned FULL = 0xffffffffu;
    const int warp = threadIdx.x >> 5, lane = threadIdx.x & 31;
    const int gp = blockIdx.x*8 + warp;
    const int b  = gp >> 15;

    const float2 q = reinterpret_cast<const float2*>(g_Q + (size_t)gp*64)[lane];

    int idx = 0;
    if (lane < 16) {
        int i = gp*16 + lane;
        idx = xxs[i]*W_ + yys[i];
    }
    const float* Sb = g_S + (size_t)b*HW*64;
    const float* Rb = g_R + (size_t)b*HW*64;

    float myscore = -1e30f;
#pragma unroll
    for (int k = 0; k < 16; k++) {
        int id = __shfl_sync(FULL, idx, k);
        float2 kv = reinterpret_cast<const float2*>(Sb + (size_t)id*64)[lane];
        float s = q.x*kv.x + q.y*kv.y;
#pragma unroll
        for (int off = 16; off; off >>= 1) s += __shfl_xor_sync(FULL, s, off);
        if (lane == k) myscore = s;
    }
    float mx = myscore;
#pragma unroll
    for (int off = 8; off; off >>= 1) mx = fmaxf(mx, __shfl_xor_sync(FULL, mx, off));
    float e = expf(myscore - mx);
    float sum = e;
#pragma unroll
    for (int off = 8; off; off >>= 1) sum += __shfl_xor_sync(FULL, sum, off);
    float m = e / sum;

    float2 accv = make_float2(0.f, 0.f);
#pragma unroll
    for (int k = 0; k < 16; k++) {
        float mk = __shfl_sync(FULL, m, k);
        int   id = __shfl_sync(FULL, idx, k);
        float2 vv = reinterpret_cast<const float2*>(Rb + (size_t)id*64)[lane];
        accv.x = fmaf(mk, vv.x, accv.x);
        accv.y = fmaf(mk, vv.y, accv.y);
    }
    float r0, r1;
    const size_t o = (size_t)gp*64 + 2*lane;
    *reinterpret_cast<uint32_t*>(g_att_hi + o) = pack_hi(accv.x, accv.y, r0, r1);
    *reinterpret_cast<uint32_t*>(g_att_lo + o) = pack_lo(r0, r1);
    if (lane < 16) outM[(size_t)gp*16 + lane] = m;
}

// ---------------- fusion 1x1 HMMA: K=128 (attn 64 + x_left 64) -> 64 oc ------
#define FA_HI 0u
#define FA_LO 32768u
#define FB_HI 65536u
#define FB_LO 81920u
#define SMEM_FUSE 98304u

__global__ __launch_bounds__(512, 2)
void fuse_hmma(const float* __restrict__ fb, float* __restrict__ out)
{
    extern __shared__ __align__(16) char smem[];
    const uint32_t sb = smem_u32(smem);
    const int tid = threadIdx.x;
    const int lane = tid & 31, warp = tid >> 5;
    const int wm = warp & 3, wn = warp >> 2;
    const int mbase = wm*32, ocb = wn*16;
    const int grp = lane >> 3, row = lane & 7;
    const int p0 = blockIdx.x * 128;

    // stage A: 128 px x 16 granules (ch<64 from attn, ch>=64 from x_left bf16)
    for (int i = tid; i < 2048; i += 512) {
        const int px = i >> 4, g = i & 15;
        const uint32_t da = px*256 + ((g ^ (px & 7)) << 4);
        const size_t so = (size_t)(p0+px)*64 + (g & 7)*8;
        const __nv_bfloat16* sh = (g < 8) ? (g_att_hi + so) : (g_in_hi + so);
        const __nv_bfloat16* sl = (g < 8) ? (g_att_lo + so) : (g_in_lo + so);
        *reinterpret_cast<uint4*>(smem + FA_HI + da) = *reinterpret_cast<const uint4*>(sh);
        *reinterpret_cast<uint4*>(smem + FA_LO + da) = *reinterpret_cast<const uint4*>(sl);
    }
    // stage B: 64 oc x 16 granules
    for (int i = tid; i < 1024; i += 512) {
        const int oc = i >> 4, g = i & 15;
        const uint32_t da = oc*256 + ((g ^ (oc & 7)) << 4);
        const size_t so = (size_t)oc*128 + g*8;
        *reinterpret_cast<uint4*>(smem + FB_HI + da) = *reinterpret_cast<const uint4*>(g_wf_hi + so);
        *reinterpret_cast<uint4*>(smem + FB_LO + da) = *reinterpret_cast<const uint4*>(g_wf_lo + so);
    }
    __syncthreads();

    float d[2][2][4];
#pragma unroll
    for (int mt = 0; mt < 2; mt++)
#pragma unroll
        for (int f = 0; f < 2; f++)
#pragma unroll
            for (int j = 0; j < 4; j++) d[mt][f][j] = 0.f;

#pragma unroll
    for (int ks = 0; ks < 8; ks++) {
        uint32_t Bh[4], Bl[4];
        {
            const int oc = ocb + ((grp >> 1) << 3) + row;
            const int g  = 2*ks + (grp & 1);
            const uint32_t a = oc*256u + ((g ^ (oc & 7)) << 4);
            ldsm_x4(Bh, sb + FB_HI + a);
            ldsm_x4(Bl, sb + FB_LO + a);
        }
#pragma unroll
        for (int mt = 0; mt < 2; mt++) {
            const int m = mbase + mt*16 + ((grp & 1) << 3) + row;
            const int g = 2*ks + (grp >> 1);
            const uint32_t a = m*256u + ((g ^ (m & 7)) << 4);
            uint32_t Ah[4], Al[4];
            ldsm_x4(Ah, sb + FA_HI + a);
            ldsm_x4(Al, sb + FA_LO + a);
#pragma unroll
            for (int f = 0; f < 2; f++) {
                mma16816(d[mt][f], Ah, Bh + 2*f);
                mma16816(d[mt][f], Al, Bh + 2*f);
                mma16816(d[mt][f], Ah, Bl + 2*f);
            }
        }
    }
    __syncthreads();

    // transpose via smem -> coalesced NCHW stores
    float* sf = reinterpret_cast<float*>(smem);    // [64][132]
#pragma unroll
    for (int mt = 0; mt < 2; mt++) {
#pragma unroll
        for (int f = 0; f < 2; f++) {
#pragma unroll
            for (int half = 0; half < 2; half++) {
                const int m = mbase + mt*16 + (lane >> 2) + half*8;
                const int c = ocb + f*8 + 2*(lane & 3);
                sf[(c+0)*132 + m] = d[mt][f][2*half+0];
                sf[(c+1)*132 + m] = d[mt][f][2*half+1];
            }
        }
    }
    __syncthreads();
    const int img = p0 >> 15, pix0 = p0 & (HW-1);
    for (int i = tid; i < 8192; i += 512) {
        const int c = i >> 7, px = i & 127;
        out[(size_t)img*CHW + (size_t)c*HW + pix0 + px] = sf[c*132 + px] + fb[c];
    }
}

// -----------------------------------------------------------------------------
extern "C" void kernel_launch(void* const* d_in, const int* in_sizes, int n_in,
                              void* d_out, int out_size)
{
    const float* xl    = (const float*)d_in[0];
    const float* xr    = (const float*)d_in[1];
    const int*   xxs   = (const int*)  d_in[2];
    const int*   yys   = (const int*)  d_in[3];
    const float* rb_w1 = (const float*)d_in[5];
    const float* rb_w2 = (const float*)d_in[6];
    const float* b1_w  = (const float*)d_in[7];
    const float* b1_b  = (const float*)d_in[8];
    const float* b2_w  = (const float*)d_in[9];
    const float* b2_b  = (const float*)d_in[10];
    const float* b3_w  = (const float*)d_in[11];
    const float* b3_b  = (const float*)d_in[12];
    const float* fus_w = (const float*)d_in[13];
    const float* fus_b = (const float*)d_in[14];
    float* out = (float*)d_out;

    static int attr_set = 0;
    if (!attr_set) {
        cudaFuncSetAttribute(conv_mma_kernel,
                             cudaFuncAttributeMaxDynamicSharedMemorySize, SMEM_CONV);
        cudaFuncSetAttribute(gemm_hmma<64>,
                             cudaFuncAttributeMaxDynamicSharedMemorySize, SMEM_GEMM);
        cudaFuncSetAttribute(gemm_hmma<128>,
                             cudaFuncAttributeMaxDynamicSharedMemorySize, SMEM_GEMM);
        cudaFuncSetAttribute(fuse_hmma,
                             cudaFuncAttributeMaxDynamicSharedMemorySize, SMEM_FUSE);
        attr_set = 1;
    }

    __nv_bfloat16 *p_in_hi, *p_in_lo, *p_mid_hi, *p_mid_lo;
    __nv_bfloat16 *p_w1h, *p_w1l, *p_w2h, *p_w2l;
    __nv_bfloat16 *p_bh, *p_bl, *p_wqh, *p_wql, *p_wsrh, *p_wsrl;
    float *p_Q, *p_S, *p_R;
    cudaGetSymbolAddress((void**)&p_in_hi,  g_in_hi);
    cudaGetSymbolAddress((void**)&p_in_lo,  g_in_lo);
    cudaGetSymbolAddress((void**)&p_mid_hi, g_mid_hi);
    cudaGetSymbolAddress((void**)&p_mid_lo, g_mid_lo);
    cudaGetSymbolAddress((void**)&p_w1h, g_w1_hi);
    cudaGetSymbolAddress((void**)&p_w1l, g_w1_lo);
    cudaGetSymbolAddress((void**)&p_w2h, g_w2_hi);
    cudaGetSymbolAddress((void**)&p_w2l, g_w2_lo);
    cudaGetSymbolAddress((void**)&p_bh,  g_buf_hi);
    cudaGetSymbolAddress((void**)&p_bl,  g_buf_lo);
    cudaGetSymbolAddress((void**)&p_wqh, g_wq_hi);
    cudaGetSymbolAddress((void**)&p_wql, g_wq_lo);
    cudaGetSymbolAddress((void**)&p_wsrh, g_wsr_hi);
    cudaGetSymbolAddress((void**)&p_wsrl, g_wsr_lo);
    cudaGetSymbolAddress((void**)&p_Q, g_Q);
    cudaGetSymbolAddress((void**)&p_S, g_S);
    cudaGetSymbolAddress((void**)&p_R, g_R);

    prep_kernel<<<512, 256>>>(xl, xr);
    prep_w_kernel<<<144, 256>>>(rb_w1, rb_w2);
    prep_w2_kernel<<<80, 256>>>(b1_w, b2_w, b3_w, fus_w);

    conv_mma_kernel<<<296, 256, SMEM_CONV>>>(p_in_hi,  p_in_lo,  p_w1h, p_w1l, xl, xr, 0);
    conv_mma_kernel<<<296, 256, SMEM_CONV>>>(p_mid_hi, p_mid_lo, p_w2h, p_w2l, xl, xr, 1);

    // Q from buf_l (imgs 0,1); S,R from buf_r (imgs 2,3)
    gemm_hmma<64> <<<512, 512, SMEM_GEMM>>>(p_bh, p_bl, p_wqh, p_wql,
                                            b1_b, b1_b, p_Q, p_Q);
    gemm_hmma<128><<<512, 512, SMEM_GEMM>>>(p_bh + (size_t)2*HW*64, p_bl + (size_t)2*HW*64,
                                            p_wsrh, p_wsrl, b2_b, b3_b, p_S, p_R);

    attn_kernel<<<8192, 256>>>(xxs, yys, out + MOFF);
    fuse_hmma<<<512, 512, SMEM_FUSE>>>(fus_b, out);
}

// round 9
// speedup vs baseline: 3.0984x; 1.0802x over previous
#include <cuda_runtime.h>
#include <cuda_bf16.h>
#include <cstdint>

#define H_  128
#define W_  256
#define HW  32768
#define C_  64
#define CHW (C_*HW)          // 2,097,152
#define MOFF (2*CHW)         // out elements = 4,194,304

typedef unsigned long long ull;

// ---------------- mma.sync / ldmatrix helpers (baseline PTX, sm_80+) ---------
__device__ __forceinline__ uint32_t smem_u32(const void* p) {
    uint32_t a;
    asm("{ .reg .u64 t; cvta.to.shared.u64 t, %1; cvt.u32.u64 %0, t; }" : "=r"(a) : "l"(p));
    return a;
}
__device__ __forceinline__ void ldsm_x4(uint32_t* r, uint32_t addr) {
    asm volatile("ldmatrix.sync.aligned.m8n8.x4.shared.b16 {%0,%1,%2,%3}, [%4];"
        : "=r"(r[0]), "=r"(r[1]), "=r"(r[2]), "=r"(r[3]) : "r"(addr));
}
__device__ __forceinline__ void mma16816(float* d, const uint32_t* a, const uint32_t* b) {
    asm volatile("mma.sync.aligned.m16n8k16.row.col.f32.bf16.bf16.f32 "
        "{%0,%1,%2,%3}, {%4,%5,%6,%7}, {%8,%9}, {%0,%1,%2,%3};"
        : "+f"(d[0]), "+f"(d[1]), "+f"(d[2]), "+f"(d[3])
        : "r"(a[0]), "r"(a[1]), "r"(a[2]), "r"(a[3]), "r"(b[0]), "r"(b[1]));
}
__device__ __forceinline__ uint32_t pack_hi(float v0, float v1, float& r0, float& r1) {
    __nv_bfloat16 h0 = __float2bfloat16(v0);
    __nv_bfloat16 h1 = __float2bfloat16(v1);
    r0 = v0 - __bfloat162float(h0);
    r1 = v1 - __bfloat162float(h1);
    return ((uint32_t)__bfloat16_as_ushort(h1) << 16) | __bfloat16_as_ushort(h0);
}
__device__ __forceinline__ uint32_t pack_lo(float r0, float r1) {
    return ((uint32_t)__bfloat16_as_ushort(__float2bfloat16(r1)) << 16)
         | __bfloat16_as_ushort(__float2bfloat16(r0));
}

// ---------------- scratch ----------------------------------------------------
__device__ __align__(16) __nv_bfloat16 g_in_hi [4*HW*C_];   // [img][y][x][ch]
__device__ __align__(16) __nv_bfloat16 g_in_lo [4*HW*C_];
__device__ __align__(16) __nv_bfloat16 g_mid_hi[4*HW*C_];
__device__ __align__(16) __nv_bfloat16 g_mid_lo[4*HW*C_];
__device__ __align__(16) __nv_bfloat16 g_buf_hi[4*HW*C_];   // residual block out
__device__ __align__(16) __nv_bfloat16 g_buf_lo[4*HW*C_];
__device__ __align__(16) __nv_bfloat16 g_att_hi[2*HW*C_];
__device__ __align__(16) __nv_bfloat16 g_att_lo[2*HW*C_];
__device__ __align__(16) __nv_bfloat16 g_w1_hi[9*64*64];    // [tap][oc][ch]
__device__ __align__(16) __nv_bfloat16 g_w1_lo[9*64*64];
__device__ __align__(16) __nv_bfloat16 g_w2_hi[9*64*64];
__device__ __align__(16) __nv_bfloat16 g_w2_lo[9*64*64];
__device__ __align__(16) __nv_bfloat16 g_wq_hi [64*64];     // [oc][ic]
__device__ __align__(16) __nv_bfloat16 g_wq_lo [64*64];
__device__ __align__(16) __nv_bfloat16 g_wsr_hi[128*64];    // S then R
__device__ __align__(16) __nv_bfloat16 g_wsr_lo[128*64];
__device__ __align__(16) __nv_bfloat16 g_wf_hi [64*128];    // fuse [oc][ic]
__device__ __align__(16) __nv_bfloat16 g_wf_lo [64*128];
__device__ __align__(16) float g_Q[2*HW*C_];                // [p][c] fp32
__device__ __align__(16) float g_S[2*HW*C_];
__device__ __align__(16) float g_R[2*HW*C_];

// ---------------- prep: fp32 NCHW -> bf16 hi/lo [img][y][x][ch] --------------
__global__ __launch_bounds__(256)
void prep_kernel(const float* __restrict__ xl, const float* __restrict__ xr)
{
    const int gp = blockIdx.x*256 + threadIdx.x;   // 0..4*HW-1
    const int n  = gp >> 15, pix = gp & (HW-1);
    const float* src = ((n < 2) ? (xl + n*CHW) : (xr + (n-2)*CHW)) + pix;

    uint32_t hb[32], lb[32];
#pragma unroll
    for (int j = 0; j < 32; j++) {
        float v0 = src[(size_t)(2*j)*HW];
        float v1 = src[(size_t)(2*j+1)*HW];
        float r0, r1;
        hb[j] = pack_hi(v0, v1, r0, r1);
        lb[j] = pack_lo(r0, r1);
    }
    uint4* dh = reinterpret_cast<uint4*>(g_in_hi + (size_t)gp*64);
    uint4* dl = reinterpret_cast<uint4*>(g_in_lo + (size_t)gp*64);
    const uint4* sh = reinterpret_cast<const uint4*>(hb);
    const uint4* sl = reinterpret_cast<const uint4*>(lb);
#pragma unroll
    for (int j = 0; j < 8; j++) { dh[j] = sh[j]; dl[j] = sl[j]; }
}

// ---------------- prep conv weights: [oc][ci][tap] -> hi/lo [tap][oc][ci] ----
__global__ __launch_bounds__(256)
void prep_w_kernel(const float* __restrict__ w1, const float* __restrict__ w2)
{
    const int i = blockIdx.x*256 + threadIdx.x;
    if (i >= 9*4096) return;
    const int tap = i >> 12, r = i & 4095;
    const int oc = r >> 6, ci = r & 63;
    const int src = (oc*64 + ci)*9 + tap;
    const int dst = (tap*64 + oc)*64 + ci;
    float v1 = w1[src], v2 = w2[src];
    __nv_bfloat16 h1 = __float2bfloat16(v1);
    __nv_bfloat16 h2 = __float2bfloat16(v2);
    g_w1_hi[dst] = h1;
    g_w1_lo[dst] = __float2bfloat16(v1 - __bfloat162float(h1));
    g_w2_hi[dst] = h2;
    g_w2_lo[dst] = __float2bfloat16(v2 - __bfloat162float(h2));
}

// ---------------- prep 1x1 weights (Q, S, R, fuse) ---------------------------
__global__ __launch_bounds__(256)
void prep_w2_kernel(const float* __restrict__ qw, const float* __restrict__ sw,
                    const float* __restrict__ rw, const float* __restrict__ fw)
{
    const int i = blockIdx.x*256 + threadIdx.x;
    if (i >= 20480) return;
    float v; __nv_bfloat16* dh; __nv_bfloat16* dl; int j;
    if (i < 4096)       { j = i;         v = qw[j]; dh = g_wq_hi  + j;      dl = g_wq_lo  + j; }
    else if (i < 8192)  { j = i - 4096;  v = sw[j]; dh = g_wsr_hi + j;      dl = g_wsr_lo + j; }
    else if (i < 12288) { j = i - 8192;  v = rw[j]; dh = g_wsr_hi + 4096+j; dl = g_wsr_lo + 4096+j; }
    else                { j = i - 12288; v = fw[j]; dh = g_wf_hi  + j;      dl = g_wf_lo  + j; }
    __nv_bfloat16 h = __float2bfloat16(v);
    *dh = h;
    *dl = __float2bfloat16(v - __bfloat162float(h));
}

// ---------------- HMMA 3x3 conv: row-pair tiles + rolling A window -----------
// CTA = 256 thr (8 warps: 4 M x 2 N), strip = 64 px, segment = 8 rows (4 pairs)
// A: 4-plane rolling ring (rows y-1..y+2), hi & lo. B: per-tap ping-pong.
#define APX2  66
#define AROW2 (APX2*128)               // 8448 bytes per plane per half
#define CA_HI 0u
#define CA_LO (4u*AROW2)               // 33792
#define CB_OFF (8u*AROW2)              // 67584
#define SMEM_CONV (CB_OFF + 32768u)    // 100352

__global__ __launch_bounds__(256, 2)
void conv_mma_kernel(const __nv_bfloat16* __restrict__ in_hi,
                     const __nv_bfloat16* __restrict__ in_lo,
                     const __nv_bfloat16* __restrict__ w_hi,
                     const __nv_bfloat16* __restrict__ w_lo,
                     const float* __restrict__ xl, const float* __restrict__ xr,
                     int layer)
{
    extern __shared__ __align__(16) char smem[];
    const uint32_t sb = smem_u32(smem);
    const int tid = threadIdx.x;
    const int lane = tid & 31, warp = tid >> 5;
    const int wm = warp & 3, wn = warp >> 2;
    const int mbase = wm*16, ocb = wn*32;
    const int grp = lane >> 3, row = lane & 7;

    const int cta = blockIdx.x;           // 256 CTAs = img(4) x strip(4) x seg(16)
    const int n  = cta >> 6;
    const int x0 = ((cta >> 4) & 3) * 64;
    const int y0 = (cta & 15) * 8;

    // stage one input row gy (zero-pad OOB) into plane (gy+4)&3
    auto stage_row = [&](int gy) {
        const uint32_t pl = (uint32_t)((gy + 4) & 3) * AROW2;
        for (int i = tid; i < 528; i += 256) {
            const int px = i >> 3, g = i & 7;
            const int gx = x0 + px - 1;
            const bool ok = ((unsigned)gy < (unsigned)H_) && ((unsigned)gx < (unsigned)W_);
            const size_t go = (((size_t)(n*H_ + gy))*W_ + gx)*64 + g*8;
            const uint32_t da = pl + px*128 + ((g ^ (px & 7)) << 4);
            const uint4 z = make_uint4(0,0,0,0);
            *reinterpret_cast<uint4*>(smem + CA_HI + da) =
                ok ? *reinterpret_cast<const uint4*>(in_hi + go) : z;
            *reinterpret_cast<uint4*>(smem + CA_LO + da) =
                ok ? *reinterpret_cast<const uint4*>(in_lo + go) : z;
        }
    };
    auto stage_B = [&](int tap, int buf) {
        const uint32_t bdst = CB_OFF + (uint32_t)buf*16384u;
        for (int i = tid; i < 512; i += 256) {
            const int oc = i >> 3, g = i & 7;
            const uint32_t da = bdst + oc*128 + ((g ^ (oc & 7)) << 4);
            const size_t so = ((size_t)(tap*64 + oc))*64 + g*8;
            *reinterpret_cast<uint4*>(smem + da) =
                *reinterpret_cast<const uint4*>(w_hi + so);
            *reinterpret_cast<uint4*>(smem + da + 8192u) =
                *reinterpret_cast<const uint4*>(w_lo + so);
        }
    };

    // initial staging: rows y0-1..y0+2, B tap0 into buf 0
    stage_row(y0 - 1); stage_row(y0); stage_row(y0 + 1); stage_row(y0 + 2);
    stage_B(0, 0);
    __syncthreads();

    for (int p = 0; p < 4; p++) {
        const int yp = y0 + 2*p;
        if (p > 0) {                      // 2 new rows for this pair
            stage_row(yp + 1); stage_row(yp + 2);
            __syncthreads();
        }

        float d[2][4][4];
#pragma unroll
        for (int t2 = 0; t2 < 2; t2++)
#pragma unroll
            for (int f = 0; f < 4; f++)
#pragma unroll
                for (int j = 0; j < 4; j++) d[t2][f][j] = 0.f;

        for (int tap = 0; tap < 9; tap++) {
            // prefetch next tap (tap 8 prefetches tap0 for the next pair)
            stage_B((tap + 1) % 9, (p + tap + 1) & 1);

            const int dy = tap/3 - 1, dx = tap%3 - 1;
            const uint32_t bcur = CB_OFF + (uint32_t)((p + tap) & 1)*16384u;

#pragma unroll
            for (int ks = 0; ks < 4; ks++) {
                uint32_t Bh[8], Bl[8];
                {
                    const int oc0 = ocb + ((grp >> 1) << 3) + row;
                    const int gB  = 2*ks + (grp & 1);
                    const uint32_t a0 = oc0*128u + ((gB ^ (oc0 & 7)) << 4);
                    ldsm_x4(Bh,     sb + bcur + a0);
                    ldsm_x4(Bl,     sb + bcur + 8192u + a0);
                    const int oc1 = oc0 + 16;
                    const uint32_t a1 = oc1*128u + ((gB ^ (oc1 & 7)) << 4);
                    ldsm_x4(Bh + 4, sb + bcur + a1);
                    ldsm_x4(Bl + 4, sb + bcur + 8192u + a1);
                }
#pragma unroll
                for (int t2 = 0; t2 < 2; t2++) {
                    const uint32_t pl = (uint32_t)((yp + t2 + dy + 4) & 3) * AROW2;
                    const int m  = mbase + ((grp & 1) << 3) + row;
                    const int gA = 2*ks + (grp >> 1);
                    const int px = m + dx + 1;
                    const uint32_t aoff = pl + px*128u + ((gA ^ (px & 7)) << 4);
                    uint32_t Ah[4], Al[4];
                    ldsm_x4(Ah, sb + CA_HI + aoff);
                    ldsm_x4(Al, sb + CA_LO + aoff);
#pragma unroll
                    for (int f = 0; f < 4; f++) {
                        mma16816(d[t2][f], Ah, Bh + 2*f);
                        mma16816(d[t2][f], Al, Bh + 2*f);
                        mma16816(d[t2][f], Ah, Bl + 2*f);
                    }
                }
            }
            __syncthreads();
        }

        // ---- epilogue (registers -> global; no smem) ------------------------
        const int mrow = (lane >> 2);
        const int cpair = 2*(lane & 3);
#pragma unroll
        for (int t2 = 0; t2 < 2; t2++) {
            const int y = yp + t2;
            if (layer == 0) {
#pragma unroll
                for (int f = 0; f < 4; f++) {
#pragma unroll
                    for (int half = 0; half < 2; half++) {
                        float v0 = d[t2][f][2*half+0], v1 = d[t2][f][2*half+1];
                        v0 = v0 > 0.f ? v0 : 0.1f*v0;
                        v1 = v1 > 0.f ? v1 : 0.1f*v1;
                        const int m = mbase + mrow + half*8;
                        const int c = ocb + f*8 + cpair;
                        const size_t o = (((size_t)(n*H_ + y))*W_ + x0 + m)*64 + c;
                        float r0, r1;
                        *reinterpret_cast<uint32_t*>(g_mid_hi + o) = pack_hi(v0, v1, r0, r1);
                        *reinterpret_cast<uint32_t*>(g_mid_lo + o) = pack_lo(r0, r1);
                    }
                }
            } else {
                const float* res = (n < 2) ? (xl + n*CHW) : (xr + (n-2)*CHW);
#pragma unroll
                for (int f = 0; f < 4; f++) {
#pragma unroll
                    for (int half = 0; half < 2; half++) {
                        const int m = mbase + mrow + half*8;
                        const int c = ocb + f*8 + cpair;
                        const int pix = y*W_ + x0 + m;
                        float v0 = d[t2][f][2*half+0] + res[(size_t)c*HW + pix];
                        float v1 = d[t2][f][2*half+1] + res[(size_t)(c+1)*HW + pix];
                        const size_t o = ((size_t)n*HW + pix)*64 + c;
                        float r0, r1;
                        *reinterpret_cast<uint32_t*>(g_buf_hi + o) = pack_hi(v0, v1, r0, r1);
                        *reinterpret_cast<uint32_t*>(g_buf_lo + o) = pack_lo(r0, r1);
                    }
                }
            }
        }
    }
}

// ---------------- generic HMMA GEMM: [65536 px] x NOC oc, K=64 ---------------
#define QA_HI 0u
#define QA_LO 16384u
#define QB_HI 32768u
#define QB_LO (32768u + 16384u)
#define SMEM_GEMM 65536u

template<int NOC>
__global__ __launch_bounds__(512, 2)
void gemm_hmma(const __nv_bfloat16* __restrict__ a_hi,
               const __nv_bfloat16* __restrict__ a_lo,
               const __nv_bfloat16* __restrict__ w_hi,
               const __nv_bfloat16* __restrict__ w_lo,
               const float* __restrict__ biasA, const float* __restrict__ biasB,
               float* __restrict__ outA, float* __restrict__ outB)
{
    extern __shared__ __align__(16) char smem[];
    const uint32_t sb = smem_u32(smem);
    const int tid = threadIdx.x;
    const int lane = tid & 31, warp = tid >> 5;
    const int wm = warp & 3, wn = warp >> 2;
    constexpr int NW  = NOC/4;
    constexpr int L16 = NW/16;
    constexpr int F8  = NW/8;
    const int mbase = wm*32, ocb = wn*NW;
    const int grp = lane >> 3, row = lane & 7;
    const int p0 = blockIdx.x * 128;

    for (int i = tid; i < 1024; i += 512) {
        const int px = i >> 3, g = i & 7;
        const uint32_t da = px*128 + ((g ^ (px & 7)) << 4);
        const size_t so = (size_t)(p0+px)*64 + g*8;
        *reinterpret_cast<uint4*>(smem + QA_HI + da) = *reinterpret_cast<const uint4*>(a_hi + so);
        *reinterpret_cast<uint4*>(smem + QA_LO + da) = *reinterpret_cast<const uint4*>(a_lo + so);
    }
    for (int i = tid; i < NOC*8; i += 512) {
        const int oc = i >> 3, g = i & 7;
        const uint32_t da = oc*128 + ((g ^ (oc & 7)) << 4);
        const size_t so = (size_t)oc*64 + g*8;
        *reinterpret_cast<uint4*>(smem + QB_HI + da) = *reinterpret_cast<const uint4*>(w_hi + so);
        *reinterpret_cast<uint4*>(smem + QB_LO + da) = *reinterpret_cast<const uint4*>(w_lo + so);
    }
    __syncthreads();

    float d[2][F8][4];
#pragma unroll
    for (int mt = 0; mt < 2; mt++)
#pragma unroll
        for (int f = 0; f < F8; f++)
#pragma unroll
            for (int j = 0; j < 4; j++) d[mt][f][j] = 0.f;

#pragma unroll
    for (int ks = 0; ks < 4; ks++) {
        uint32_t Bh[4*L16], Bl[4*L16];
#pragma unroll
        for (int l = 0; l < L16; l++) {
            const int oc = ocb + l*16 + ((grp >> 1) << 3) + row;
            const int g  = 2*ks + (grp & 1);
            const uint32_t a = oc*128u + ((g ^ (oc & 7)) << 4);
            ldsm_x4(Bh + 4*l, sb + QB_HI + a);
            ldsm_x4(Bl + 4*l, sb + QB_LO + a);
        }
#pragma unroll
        for (int mt = 0; mt < 2; mt++) {
            const int m = mbase + mt*16 + ((grp & 1) << 3) + row;
            const int g = 2*ks + (grp >> 1);
            const uint32_t a = m*128u + ((g ^ (m & 7)) << 4);
            uint32_t Ah[4], Al[4];
            ldsm_x4(Ah, sb + QA_HI + a);
            ldsm_x4(Al, sb + QA_LO + a);
#pragma unroll
            for (int f = 0; f < F8; f++) {
                mma16816(d[mt][f], Ah, Bh + 2*f);
                mma16816(d[mt][f], Al, Bh + 2*f);
                mma16816(d[mt][f], Ah, Bl + 2*f);
            }
        }
    }

#pragma unroll
    for (int mt = 0; mt < 2; mt++) {
#pragma unroll
        for (int f = 0; f < F8; f++) {
#pragma unroll
            for (int half = 0; half < 2; half++) {
                const int m = mbase + mt*16 + (lane >> 2) + half*8;
                const int c = ocb + f*8 + 2*(lane & 3);
                const float* bias = (c < 64) ? biasA : biasB;
                const int col = c & 63;
                float v0 = d[mt][f][2*half+0] + bias[col];
                float v1 = d[mt][f][2*half+1] + bias[col+1];
                float* o = ((c < 64) ? outA : outB) + (size_t)(p0+m)*64 + col;
                *reinterpret_cast<float2*>(o) = make_float2(v0, v1);
            }
        }
    }
}

// ---------------- attention: warp per pixel, K = 16 --------------------------
__global__ __launch_bounds__(256)
void attn_kernel(const int* __restrict__ xxs, const int* __restrict__ yys,
                 float* __restrict__ outM)
{
    const unsigned FULL = 0xffffffffu;
    const int warp = threadIdx.x >> 5, lane = threadIdx.x & 31;
    const int gp = blockIdx.x*8 + warp;
    const int b  = gp >> 15;

    const float2 q = reinterpret_cast<const float2*>(g_Q + (size_t)gp*64)[lane];

    int idx = 0;
    if (lane < 16) {
        int i = gp*16 + lane;
        idx = xxs[i]*W_ + yys[i];
    }
    const float* Sb = g_S + (size_t)b*HW*64;
    const float* Rb = g_R + (size_t)b*HW*64;

    float myscore = -1e30f;
#pragma unroll
    for (int k = 0; k < 16; k++) {
        int id = __shfl_sync(FULL, idx, k);
        float2 kv = reinterpret_cast<const float2*>(Sb + (size_t)id*64)[lane];
        float s = q.x*kv.x + q.y*kv.y;
#pragma unroll
        for (int off = 16; off; off >>= 1) s += __shfl_xor_sync(FULL, s, off);
        if (lane == k) myscore = s;
    }
    float mx = myscore;
#pragma unroll
    for (int off = 8; off; off >>= 1) mx = fmaxf(mx, __shfl_xor_sync(FULL, mx, off));
    float e = expf(myscore - mx);
    float sum = e;
#pragma unroll
    for (int off = 8; off; off >>= 1) sum += __shfl_xor_sync(FULL, sum, off);
    float m = e / sum;

    float2 accv = make_float2(0.f, 0.f);
#pragma unroll
    for (int k = 0; k < 16; k++) {
        float mk = __shfl_sync(FULL, m, k);
        int   id = __shfl_sync(FULL, idx, k);
        float2 vv = reinterpret_cast<const float2*>(Rb + (size_t)id*64)[lane];
        accv.x = fmaf(mk, vv.x, accv.x);
        accv.y = fmaf(mk, vv.y, accv.y);
    }
    float r0, r1;
    const size_t o = (size_t)gp*64 + 2*lane;
    *reinterpret_cast<uint32_t*>(g_att_hi + o) = pack_hi(accv.x, accv.y, r0, r1);
    *reinterpret_cast<uint32_t*>(g_att_lo + o) = pack_lo(r0, r1);
    if (lane < 16) outM[(size_t)gp*16 + lane] = m;
}

// ---------------- fusion 1x1 HMMA: K=128 (attn 64 + x_left 64) -> 64 oc ------
#define FA_HI 0u
#define FA_LO 32768u
#define FB_HI 65536u
#define FB_LO 81920u
#define SMEM_FUSE 98304u

__global__ __launch_bounds__(512, 2)
void fuse_hmma(const float* __restrict__ fb, float* __restrict__ out)
{
    extern __shared__ __align__(16) char smem[];
    const uint32_t sb = smem_u32(smem);
    const int tid = threadIdx.x;
    const int lane = tid & 31, warp = tid >> 5;
    const int wm = warp & 3, wn = warp >> 2;
    const int mbase = wm*32, ocb = wn*16;
    const int grp = lane >> 3, row = lane & 7;
    const int p0 = blockIdx.x * 128;

    for (int i = tid; i < 2048; i += 512) {
        const int px = i >> 4, g = i & 15;
        const uint32_t da = px*256 + ((g ^ (px & 7)) << 4);
        const size_t so = (size_t)(p0+px)*64 + (g & 7)*8;
        const __nv_bfloat16* sh = (g < 8) ? (g_att_hi + so) : (g_in_hi + so);
        const __nv_bfloat16* sl = (g < 8) ? (g_att_lo + so) : (g_in_lo + so);
        *reinterpret_cast<uint4*>(smem + FA_HI + da) = *reinterpret_cast<const uint4*>(sh);
        *reinterpret_cast<uint4*>(smem + FA_LO + da) = *reinterpret_cast<const uint4*>(sl);
    }
    for (int i = tid; i < 1024; i += 512) {
        const int oc = i >> 4, g = i & 15;
        const uint32_t da = oc*256 + ((g ^ (oc & 7)) << 4);
        const size_t so = (size_t)oc*128 + g*8;
        *reinterpret_cast<uint4*>(smem + FB_HI + da) = *reinterpret_cast<const uint4*>(g_wf_hi + so);
        *reinterpret_cast<uint4*>(smem + FB_LO + da) = *reinterpret_cast<const uint4*>(g_wf_lo + so);
    }
    __syncthreads();

    float d[2][2][4];
#pragma unroll
    for (int mt = 0; mt < 2; mt++)
#pragma unroll
        for (int f = 0; f < 2; f++)
#pragma unroll
            for (int j = 0; j < 4; j++) d[mt][f][j] = 0.f;

#pragma unroll
    for (int ks = 0; ks < 8; ks++) {
        uint32_t Bh[4], Bl[4];
        {
            const int oc = ocb + ((grp >> 1) << 3) + row;
            const int g  = 2*ks + (grp & 1);
            const uint32_t a = oc*256u + ((g ^ (oc & 7)) << 4);
            ldsm_x4(Bh, sb + FB_HI + a);
            ldsm_x4(Bl, sb + FB_LO + a);
        }
#pragma unroll
        for (int mt = 0; mt < 2; mt++) {
            const int m = mbase + mt*16 + ((grp & 1) << 3) + row;
            const int g = 2*ks + (grp >> 1);
            const uint32_t a = m*256u + ((g ^ (m & 7)) << 4);
            uint32_t Ah[4], Al[4];
            ldsm_x4(Ah, sb + FA_HI + a);
            ldsm_x4(Al, sb + FA_LO + a);
#pragma unroll
            for (int f = 0; f < 2; f++) {
                mma16816(d[mt][f], Ah, Bh + 2*f);
                mma16816(d[mt][f], Al, Bh + 2*f);
                mma16816(d[mt][f], Ah, Bl + 2*f);
            }
        }
    }
    __syncthreads();

    float* sf = reinterpret_cast<float*>(smem);    // [64][132]
#pragma unroll
    for (int mt = 0; mt < 2; mt++) {
#pragma unroll
        for (int f = 0; f < 2; f++) {
#pragma unroll
            for (int half = 0; half < 2; half++) {
                const int m = mbase + mt*16 + (lane >> 2) + half*8;
                const int c = ocb + f*8 + 2*(lane & 3);
                sf[(c+0)*132 + m] = d[mt][f][2*half+0];
                sf[(c+1)*132 + m] = d[mt][f][2*half+1];
            }
        }
    }
    __syncthreads();
    const int img = p0 >> 15, pix0 = p0 & (HW-1);
    for (int i = tid; i < 8192; i += 512) {
        const int c = i >> 7, px = i & 127;
        out[(size_t)img*CHW + (size_t)c*HW + pix0 + px] = sf[c*132 + px] + fb[c];
    }
}

// -----------------------------------------------------------------------------
extern "C" void kernel_launch(void* const* d_in, const int* in_sizes, int n_in,
                              void* d_out, int out_size)
{
    const float* xl    = (const float*)d_in[0];
    const float* xr    = (const float*)d_in[1];
    const int*   xxs   = (const int*)  d_in[2];
    const int*   yys   = (const int*)  d_in[3];
    const float* rb_w1 = (const float*)d_in[5];
    const float* rb_w2 = (const float*)d_in[6];
    const float* b1_w  = (const float*)d_in[7];
    const float* b1_b  = (const float*)d_in[8];
    const float* b2_w  = (const float*)d_in[9];
    const float* b2_b  = (const float*)d_in[10];
    const float* b3_w  = (const float*)d_in[11];
    const float* b3_b  = (const float*)d_in[12];
    const float* fus_w = (const float*)d_in[13];
    const float* fus_b = (const float*)d_in[14];
    float* out = (float*)d_out;

    static int attr_set = 0;
    if (!attr_set) {
        cudaFuncSetAttribute(conv_mma_kernel,
                             cudaFuncAttributeMaxDynamicSharedMemorySize, SMEM_CONV);
        cudaFuncSetAttribute(gemm_hmma<64>,
                             cudaFuncAttributeMaxDynamicSharedMemorySize, SMEM_GEMM);
        cudaFuncSetAttribute(gemm_hmma<128>,
                             cudaFuncAttributeMaxDynamicSharedMemorySize, SMEM_GEMM);
        cudaFuncSetAttribute(fuse_hmma,
                             cudaFuncAttributeMaxDynamicSharedMemorySize, SMEM_FUSE);
        attr_set = 1;
    }

    __nv_bfloat16 *p_in_hi, *p_in_lo, *p_mid_hi, *p_mid_lo;
    __nv_bfloat16 *p_w1h, *p_w1l, *p_w2h, *p_w2l;
    __nv_bfloat16 *p_bh, *p_bl, *p_wqh, *p_wql, *p_wsrh, *p_wsrl;
    float *p_Q, *p_S, *p_R;
    cudaGetSymbolAddress((void**)&p_in_hi,  g_in_hi);
    cudaGetSymbolAddress((void**)&p_in_lo,  g_in_lo);
    cudaGetSymbolAddress((void**)&p_mid_hi, g_mid_hi);
    cudaGetSymbolAddress((void**)&p_mid_lo, g_mid_lo);
    cudaGetSymbolAddress((void**)&p_w1h, g_w1_hi);
    cudaGetSymbolAddress((void**)&p_w1l, g_w1_lo);
    cudaGetSymbolAddress((void**)&p_w2h, g_w2_hi);
    cudaGetSymbolAddress((void**)&p_w2l, g_w2_lo);
    cudaGetSymbolAddress((void**)&p_bh,  g_buf_hi);
    cudaGetSymbolAddress((void**)&p_bl,  g_buf_lo);
    cudaGetSymbolAddress((void**)&p_wqh, g_wq_hi);
    cudaGetSymbolAddress((void**)&p_wql, g_wq_lo);
    cudaGetSymbolAddress((void**)&p_wsrh, g_wsr_hi);
    cudaGetSymbolAddress((void**)&p_wsrl, g_wsr_lo);
    cudaGetSymbolAddress((void**)&p_Q, g_Q);
    cudaGetSymbolAddress((void**)&p_S, g_S);
    cudaGetSymbolAddress((void**)&p_R, g_R);

    prep_kernel<<<512, 256>>>(xl, xr);
    prep_w_kernel<<<144, 256>>>(rb_w1, rb_w2);
    prep_w2_kernel<<<80, 256>>>(b1_w, b2_w, b3_w, fus_w);

    conv_mma_kernel<<<256, 256, SMEM_CONV>>>(p_in_hi,  p_in_lo,  p_w1h, p_w1l, xl, xr, 0);
    conv_mma_kernel<<<256, 256, SMEM_CONV>>>(p_mid_hi, p_mid_lo, p_w2h, p_w2l, xl, xr, 1);

    gemm_hmma<64> <<<512, 512, SMEM_GEMM>>>(p_bh, p_bl, p_wqh, p_wql,
                                            b1_b, b1_b, p_Q, p_Q);
    gemm_hmma<128><<<512, 512, SMEM_GEMM>>>(p_bh + (size_t)2*HW*64, p_bl + (size_t)2*HW*64,
                                            p_wsrh, p_wsrl, b2_b, b3_b, p_S, p_R);

    attn_kernel<<<8192, 256>>>(xxs, yys, out + MOFF);
    fuse_hmma<<<512, 512, SMEM_FUSE>>>(fus_b, out);
}

// round 12
// speedup vs baseline: 3.7690x; 1.2164x over previous
#include <cuda_runtime.h>
#include <cuda_fp16.h>
#include <cstdint>

#define H_  128
#define W_  256
#define HW  32768
#define C_  64
#define CHW (C_*HW)          // 2,097,152
#define MOFF (2*CHW)         // out elements = 4,194,304

// ---------------- mma.sync / ldmatrix helpers (baseline PTX, sm_80+) ---------
__device__ __forceinline__ uint32_t smem_u32(const void* p) {
    uint32_t a;
    asm("{ .reg .u64 t; cvta.to.shared.u64 t, %1; cvt.u32.u64 %0, t; }" : "=r"(a) : "l"(p));
    return a;
}
__device__ __forceinline__ void ldsm_x4(uint32_t* r, uint32_t addr) {
    asm volatile("ldmatrix.sync.aligned.m8n8.x4.shared.b16 {%0,%1,%2,%3}, [%4];"
        : "=r"(r[0]), "=r"(r[1]), "=r"(r[2]), "=r"(r[3]) : "r"(addr));
}
__device__ __forceinline__ void mma16816(float* d, const uint32_t* a, const uint32_t* b) {
    asm volatile("mma.sync.aligned.m16n8k16.row.col.f32.f16.f16.f32 "
        "{%0,%1,%2,%3}, {%4,%5,%6,%7}, {%8,%9}, {%0,%1,%2,%3};"
        : "+f"(d[0]), "+f"(d[1]), "+f"(d[2]), "+f"(d[3])
        : "r"(a[0]), "r"(a[1]), "r"(a[2]), "r"(a[3]), "r"(b[0]), "r"(b[1]));
}
// fp16 2-term split helpers: hi = rn(v), lo = rn(v - hi)
__device__ __forceinline__ uint32_t pack_hi(float v0, float v1, float& r0, float& r1) {
    __half h0 = __float2half_rn(v0);
    __half h1 = __float2half_rn(v1);
    r0 = v0 - __half2float(h0);
    r1 = v1 - __half2float(h1);
    return ((uint32_t)__half_as_ushort(h1) << 16) | __half_as_ushort(h0);
}
__device__ __forceinline__ uint32_t pack_lo(float r0, float r1) {
    return ((uint32_t)__half_as_ushort(__float2half_rn(r1)) << 16)
         | __half_as_ushort(__float2half_rn(r0));
}

// ---------------- scratch ----------------------------------------------------
__device__ __align__(16) __half g_in_hi [4*HW*C_];   // [img][y][x][ch]
__device__ __align__(16) __half g_in_lo [4*HW*C_];
__device__ __align__(16) __half g_mid_hi[4*HW*C_];
__device__ __align__(16) __half g_mid_lo[4*HW*C_];
__device__ __align__(16) __half g_buf_hi[4*HW*C_];   // residual block out
__device__ __align__(16) __half g_buf_lo[4*HW*C_];
__device__ __align__(16) __half g_att_hi[2*HW*C_];
__device__ __align__(16) __half g_att_lo[2*HW*C_];
__device__ __align__(16) __half g_w1_hi[9*64*64];    // [tap][oc][ch]
__device__ __align__(16) __half g_w2_hi[9*64*64];
__device__ __align__(16) __half g_wq_hi [64*64];     // [oc][ic]
__device__ __align__(16) __half g_wsr_hi[128*64];    // S then R
__device__ __align__(16) __half g_wf_hi [64*128];    // fuse [oc][ic]
__device__ __align__(16) float g_Q[2*HW*C_];         // [p][c] fp32
__device__ __align__(16) float g_S[2*HW*C_];
__device__ __align__(16) float g_R[2*HW*C_];

// ---------------- prep: fp32 NCHW -> fp16 hi/lo [img][y][x][ch] --------------
__global__ __launch_bounds__(256)
void prep_kernel(const float* __restrict__ xl, const float* __restrict__ xr)
{
    const int gp = blockIdx.x*256 + threadIdx.x;   // 0..4*HW-1
    const int n  = gp >> 15, pix = gp & (HW-1);
    const float* src = ((n < 2) ? (xl + n*CHW) : (xr + (n-2)*CHW)) + pix;

    uint32_t hb[32], lb[32];
#pragma unroll
    for (int j = 0; j < 32; j++) {
        float v0 = src[(size_t)(2*j)*HW];
        float v1 = src[(size_t)(2*j+1)*HW];
        float r0, r1;
        hb[j] = pack_hi(v0, v1, r0, r1);
        lb[j] = pack_lo(r0, r1);
    }
    uint4* dh = reinterpret_cast<uint4*>(g_in_hi + (size_t)gp*64);
    uint4* dl = reinterpret_cast<uint4*>(g_in_lo + (size_t)gp*64);
    const uint4* sh = reinterpret_cast<const uint4*>(hb);
    const uint4* sl = reinterpret_cast<const uint4*>(lb);
#pragma unroll
    for (int j = 0; j < 8; j++) { dh[j] = sh[j]; dl[j] = sl[j]; }
}

// ---------------- prep conv weights: [oc][ci][tap] -> fp16 [tap][oc][ci] -----
__global__ __launch_bounds__(256)
void prep_w_kernel(const float* __restrict__ w1, const float* __restrict__ w2)
{
    const int i = blockIdx.x*256 + threadIdx.x;
    if (i >= 9*4096) return;
    const int tap = i >> 12, r = i & 4095;
    const int oc = r >> 6, ci = r & 63;
    const int src = (oc*64 + ci)*9 + tap;
    const int dst = (tap*64 + oc)*64 + ci;
    g_w1_hi[dst] = __float2half_rn(w1[src]);
    g_w2_hi[dst] = __float2half_rn(w2[src]);
}

// ---------------- prep 1x1 weights (Q, S, R, fuse) ---------------------------
__global__ __launch_bounds__(256)
void prep_w2_kernel(const float* __restrict__ qw, const float* __restrict__ sw,
                    const float* __restrict__ rw, const float* __restrict__ fw)
{
    const int i = blockIdx.x*256 + threadIdx.x;
    if (i >= 20480) return;
    if (i < 4096)       g_wq_hi [i]          = __float2half_rn(qw[i]);
    else if (i < 8192)  g_wsr_hi[i - 4096]   = __float2half_rn(sw[i - 4096]);
    else if (i < 12288) g_wsr_hi[4096 + i-8192] = __float2half_rn(rw[i - 8192]);
    else                g_wf_hi [i - 12288]  = __float2half_rn(fw[i - 12288]);
}

// ---------------- HMMA 3x3 conv: row-pair tiles + rolling A window -----------
// CTA = 256 thr (8 warps: 4 M x 2 N), strip = 64 px, segment = 8 rows (4 pairs)
// A: 4-plane rolling ring (rows y-1..y+2), hi & lo fp16. B: hi only, ping-pong.
#define APX2  66
#define AROW2 (APX2*128)               // 8448 bytes per plane per half
#define CA_HI 0u
#define CA_LO (4u*AROW2)               // 33792
#define CB_OFF (8u*AROW2)              // 67584
#define SMEM_CONV (CB_OFF + 16384u)    // 83968

__global__ __launch_bounds__(256, 2)
void conv_mma_kernel(const __half* __restrict__ in_hi,
                     const __half* __restrict__ in_lo,
                     const __half* __restrict__ w_hi,
                     const float* __restrict__ xl, const float* __restrict__ xr,
                     int layer)
{
    extern __shared__ __align__(16) char smem[];
    const uint32_t sb = smem_u32(smem);
    const int tid = threadIdx.x;
    const int lane = tid & 31, warp = tid >> 5;
    const int wm = warp & 3, wn = warp >> 2;
    const int mbase = wm*16, ocb = wn*32;
    const int grp = lane >> 3, row = lane & 7;

    const int cta = blockIdx.x;           // 256 CTAs = img(4) x strip(4) x seg(16)
    const int n  = cta >> 6;
    const int x0 = ((cta >> 4) & 3) * 64;
    const int y0 = (cta & 15) * 8;

    auto stage_row = [&](int gy) {
        const uint32_t pl = (uint32_t)((gy + 4) & 3) * AROW2;
        for (int i = tid; i < 528; i += 256) {
            const int px = i >> 3, g = i & 7;
            const int gx = x0 + px - 1;
            const bool ok = ((unsigned)gy < (unsigned)H_) && ((unsigned)gx < (unsigned)W_);
            const size_t go = (((size_t)(n*H_ + gy))*W_ + gx)*64 + g*8;
            const uint32_t da = pl + px*128 + ((g ^ (px & 7)) << 4);
            const uint4 z = make_uint4(0,0,0,0);
            *reinterpret_cast<uint4*>(smem + CA_HI + da) =
                ok ? *reinterpret_cast<const uint4*>(in_hi + go) : z;
            *reinterpret_cast<uint4*>(smem + CA_LO + da) =
                ok ? *reinterpret_cast<const uint4*>(in_lo + go) : z;
        }
    };
    auto stage_B = [&](int tap, int buf) {
        const uint32_t bdst = CB_OFF + (uint32_t)buf*8192u;
        for (int i = tid; i < 512; i += 256) {
            const int oc = i >> 3, g = i & 7;
            const uint32_t da = bdst + oc*128 + ((g ^ (oc & 7)) << 4);
            const size_t so = ((size_t)(tap*64 + oc))*64 + g*8;
            *reinterpret_cast<uint4*>(smem + da) =
                *reinterpret_cast<const uint4*>(w_hi + so);
        }
    };

    stage_row(y0 - 1); stage_row(y0); stage_row(y0 + 1); stage_row(y0 + 2);
    stage_B(0, 0);
    __syncthreads();

    for (int p = 0; p < 4; p++) {
        const int yp = y0 + 2*p;
        if (p > 0) {
            stage_row(yp + 1); stage_row(yp + 2);
            __syncthreads();
        }

        float d[2][4][4];
#pragma unroll
        for (int t2 = 0; t2 < 2; t2++)
#pragma unroll
            for (int f = 0; f < 4; f++)
#pragma unroll
                for (int j = 0; j < 4; j++) d[t2][f][j] = 0.f;

        for (int tap = 0; tap < 9; tap++) {
            stage_B((tap + 1) % 9, (p + tap + 1) & 1);

            const int dy = tap/3 - 1, dx = tap%3 - 1;
            const uint32_t bcur = CB_OFF + (uint32_t)((p + tap) & 1)*8192u;

#pragma unroll
            for (int ks = 0; ks < 4; ks++) {
                uint32_t Bh[8];
                {
                    const int oc0 = ocb + ((grp >> 1) << 3) + row;
                    const int gB  = 2*ks + (grp & 1);
                    const uint32_t a0 = oc0*128u + ((gB ^ (oc0 & 7)) << 4);
                    ldsm_x4(Bh,     sb + bcur + a0);
                    const int oc1 = oc0 + 16;
                    const uint32_t a1 = oc1*128u + ((gB ^ (oc1 & 7)) << 4);
                    ldsm_x4(Bh + 4, sb + bcur + a1);
                }
#pragma unroll
                for (int t2 = 0; t2 < 2; t2++) {
                    const uint32_t pl = (uint32_t)((yp + t2 + dy + 4) & 3) * AROW2;
                    const int m  = mbase + ((grp & 1) << 3) + row;
                    const int gA = 2*ks + (grp >> 1);
                    const int px = m + dx + 1;
                    const uint32_t aoff = pl + px*128u + ((gA ^ (px & 7)) << 4);
                    uint32_t Ah[4], Al[4];
                    ldsm_x4(Ah, sb + CA_HI + aoff);
                    ldsm_x4(Al, sb + CA_LO + aoff);
#pragma unroll
                    for (int f = 0; f < 4; f++) {
                        mma16816(d[t2][f], Ah, Bh + 2*f);
                        mma16816(d[t2][f], Al, Bh + 2*f);
                    }
                }
            }
            __syncthreads();
        }

        // ---- epilogue -------------------------------------------------------
        const int mrow = (lane >> 2);
        const int cpair = 2*(lane & 3);
#pragma unroll
        for (int t2 = 0; t2 < 2; t2++) {
            const int y = yp + t2;
            if (layer == 0) {
#pragma unroll
                for (int f = 0; f < 4; f++) {
#pragma unroll
                    for (int half = 0; half < 2; half++) {
                        float v0 = d[t2][f][2*half+0], v1 = d[t2][f][2*half+1];
                        v0 = v0 > 0.f ? v0 : 0.1f*v0;
                        v1 = v1 > 0.f ? v1 : 0.1f*v1;
                        const int m = mbase + mrow + half*8;
                        const int c = ocb + f*8 + cpair;
                        const size_t o = (((size_t)(n*H_ + y))*W_ + x0 + m)*64 + c;
                        float r0, r1;
                        *reinterpret_cast<uint32_t*>(g_mid_hi + o) = pack_hi(v0, v1, r0, r1);
                        *reinterpret_cast<uint32_t*>(g_mid_lo + o) = pack_lo(r0, r1);
                    }
                }
            } else {
                const float* res = (n < 2) ? (xl + n*CHW) : (xr + (n-2)*CHW);
#pragma unroll
                for (int f = 0; f < 4; f++) {
#pragma unroll
                    for (int half = 0; half < 2; half++) {
                        const int m = mbase + mrow + half*8;
                        const int c = ocb + f*8 + cpair;
                        const int pix = y*W_ + x0 + m;
                        float v0 = d[t2][f][2*half+0] + res[(size_t)c*HW + pix];
                        float v1 = d[t2][f][2*half+1] + res[(size_t)(c+1)*HW + pix];
                        const size_t o = ((size_t)n*HW + pix)*64 + c;
                        float r0, r1;
                        *reinterpret_cast<uint32_t*>(g_buf_hi + o) = pack_hi(v0, v1, r0, r1);
                        *reinterpret_cast<uint32_t*>(g_buf_lo + o) = pack_lo(r0, r1);
                    }
                }
            }
        }
    }
}

// ---------------- generic HMMA GEMM: [65536 px] x NOC oc, K=64 ---------------
#define QA_HI 0u
#define QA_LO 16384u
#define QB_HI 32768u
#define SMEM_GEMM 49152u

template<int NOC>
__global__ __launch_bounds__(512, 2)
void gemm_hmma(const __half* __restrict__ a_hi,
               const __half* __restrict__ a_lo,
               const __half* __restrict__ w_hi,
               const float* __restrict__ biasA, const float* __restrict__ biasB,
               float* __restrict__ outA, float* __restrict__ outB)
{
    extern __shared__ __align__(16) char smem[];
    const uint32_t sb = smem_u32(smem);
    const int tid = threadIdx.x;
    const int lane = tid & 31, warp = tid >> 5;
    const int wm = warp & 3, wn = warp >> 2;
    constexpr int NW  = NOC/4;
    constexpr int L16 = NW/16;
    constexpr int F8  = NW/8;
    const int mbase = wm*32, ocb = wn*NW;
    const int grp = lane >> 3, row = lane & 7;
    const int p0 = blockIdx.x * 128;

    for (int i = tid; i < 1024; i += 512) {
        const int px = i >> 3, g = i & 7;
        const uint32_t da = px*128 + ((g ^ (px & 7)) << 4);
        const size_t so = (size_t)(p0+px)*64 + g*8;
        *reinterpret_cast<uint4*>(smem + QA_HI + da) = *reinterpret_cast<const uint4*>(a_hi + so);
        *reinterpret_cast<uint4*>(smem + QA_LO + da) = *reinterpret_cast<const uint4*>(a_lo + so);
    }
    for (int i = tid; i < NOC*8; i += 512) {
        const int oc = i >> 3, g = i & 7;
        const uint32_t da = oc*128 + ((g ^ (oc & 7)) << 4);
        const size_t so = (size_t)oc*64 + g*8;
        *reinterpret_cast<uint4*>(smem + QB_HI + da) = *reinterpret_cast<const uint4*>(w_hi + so);
    }
    __syncthreads();

    float d[2][F8][4];
#pragma unroll
    for (int mt = 0; mt < 2; mt++)
#pragma unroll
        for (int f = 0; f < F8; f++)
#pragma unroll
            for (int j = 0; j < 4; j++) d[mt][f][j] = 0.f;

#pragma unroll
    for (int ks = 0; ks < 4; ks++) {
        uint32_t Bh[4*L16];
#pragma unroll
        for (int l = 0; l < L16; l++) {
            const int oc = ocb + l*16 + ((grp >> 1) << 3) + row;
            const int g  = 2*ks + (grp & 1);
            const uint32_t a = oc*128u + ((g ^ (oc & 7)) << 4);
            ldsm_x4(Bh + 4*l, sb + QB_HI + a);
        }
#pragma unroll
        for (int mt = 0; mt < 2; mt++) {
            const int m = mbase + mt*16 + ((grp & 1) << 3) + row;
            const int g = 2*ks + (grp >> 1);
            const uint32_t a = m*128u + ((g ^ (m & 7)) << 4);
            uint32_t Ah[4], Al[4];
            ldsm_x4(Ah, sb + QA_HI + a);
            ldsm_x4(Al, sb + QA_LO + a);
#pragma unroll
            for (int f = 0; f < F8; f++) {
                mma16816(d[mt][f], Ah, Bh + 2*f);
                mma16816(d[mt][f], Al, Bh + 2*f);
            }
        }
    }

#pragma unroll
    for (int mt = 0; mt < 2; mt++) {
#pragma unroll
        for (int f = 0; f < F8; f++) {
#pragma unroll
            for (int half = 0; half < 2; half++) {
                const int m = mbase + mt*16 + (lane >> 2) + half*8;
                const int c = ocb + f*8 + 2*(lane & 3);
                const float* bias = (c < 64) ? biasA : biasB;
                const int col = c & 63;
                float v0 = d[mt][f][2*half+0] + bias[col];
                float v1 = d[mt][f][2*half+1] + bias[col+1];
                float* o = ((c < 64) ? outA : outB) + (size_t)(p0+m)*64 + col;
                *reinterpret_cast<float2*>(o) = make_float2(v0, v1);
            }
        }
    }
}

// ---------------- attention: warp per pixel, K = 16 --------------------------
__global__ __launch_bounds__(256)
void attn_kernel(const int* __restrict__ xxs, const int* __restrict__ yys,
                 float* __restrict__ outM)
{
    const unsigned FULL = 0xffffffffu;
    const int warp = threadIdx.x >> 5, lane = threadIdx.x & 31;
    const int gp = blockIdx.x*8 + warp;
    const int b  = gp >> 15;

    const float2 q = reinterpret_cast<const float2*>(g_Q + (size_t)gp*64)[lane];

    int idx = 0;
    if (lane < 16) {
        int i = gp*16 + lane;
        idx = xxs[i]*W_ + yys[i];
    }
    const float* Sb = g_S + (size_t)b*HW*64;
    const float* Rb = g_R + (size_t)b*HW*64;

    float myscore = -1e30f;
#pragma unroll
    for (int k = 0; k < 16; k++) {
        int id = __shfl_sync(FULL, idx, k);
        float2 kv = reinterpret_cast<const float2*>(Sb + (size_t)id*64)[lane];
        float s = q.x*kv.x + q.y*kv.y;
#pragma unroll
        for (int off = 16; off; off >>= 1) s += __shfl_xor_sync(FULL, s, off);
        if (lane == k) myscore = s;
    }
    float mx = myscore;
#pragma unroll
    for (int off = 8; off; off >>= 1) mx = fmaxf(mx, __shfl_xor_sync(FULL, mx, off));
    float e = expf(myscore - mx);
    float sum = e;
#pragma unroll
    for (int off = 8; off; off >>= 1) sum += __shfl_xor_sync(FULL, sum, off);
    float m = e / sum;

    float2 accv = make_float2(0.f, 0.f);
#pragma unroll
    for (int k = 0; k < 16; k++) {
        float mk = __shfl_sync(FULL, m, k);
        int   id = __shfl_sync(FULL, idx, k);
        float2 vv = reinterpret_cast<const float2*>(Rb + (size_t)id*64)[lane];
        accv.x = fmaf(mk, vv.x, accv.x);
        accv.y = fmaf(mk, vv.y, accv.y);
    }
    float r0, r1;
    const size_t o = (size_t)gp*64 + 2*lane;
    *reinterpret_cast<uint32_t*>(g_att_hi + o) = pack_hi(accv.x, accv.y, r0, r1);
    *reinterpret_cast<uint32_t*>(g_att_lo + o) = pack_lo(r0, r1);
    if (lane < 16) outM[(size_t)gp*16 + lane] = m;
}

// ---------------- fusion 1x1 HMMA: K=128 (attn 64 + x_left 64) -> 64 oc ------
#define FA_HI 0u
#define FA_LO 32768u
#define FB_HI 65536u
#define SMEM_FUSE 81920u

__global__ __launch_bounds__(512, 2)
void fuse_hmma(const float* __restrict__ fb, float* __restrict__ out)
{
    extern __shared__ __align__(16) char smem[];
    const uint32_t sb = smem_u32(smem);
    const int tid = threadIdx.x;
    const int lane = tid & 31, warp = tid >> 5;
    const int wm = warp & 3, wn = warp >> 2;
    const int mbase = wm*32, ocb = wn*16;
    const int grp = lane >> 3, row = lane & 7;
    const int p0 = blockIdx.x * 128;

    for (int i = tid; i < 2048; i += 512) {
        const int px = i >> 4, g = i & 15;
        const uint32_t da = px*256 + ((g ^ (px & 7)) << 4);
        const size_t so = (size_t)(p0+px)*64 + (g & 7)*8;
        const __half* sh = (g < 8) ? (g_att_hi + so) : (g_in_hi + so);
        const __half* sl = (g < 8) ? (g_att_lo + so) : (g_in_lo + so);
        *reinterpret_cast<uint4*>(smem + FA_HI + da) = *reinterpret_cast<const uint4*>(sh);
        *reinterpret_cast<uint4*>(smem + FA_LO + da) = *reinterpret_cast<const uint4*>(sl);
    }
    for (int i = tid; i < 1024; i += 512) {
        const int oc = i >> 4, g = i & 15;
        const uint32_t da = oc*256 + ((g ^ (oc & 7)) << 4);
        const size_t so = (size_t)oc*128 + g*8;
        *reinterpret_cast<uint4*>(smem + FB_HI + da) = *reinterpret_cast<const uint4*>(g_wf_hi + so);
    }
    __syncthreads();

    float d[2][2][4];
#pragma unroll
    for (int mt = 0; mt < 2; mt++)
#pragma unroll
        for (int f = 0; f < 2; f++)
#pragma unroll
            for (int j = 0; j < 4; j++) d[mt][f][j] = 0.f;

#pragma unroll
    for (int ks = 0; ks < 8; ks++) {
        uint32_t Bh[4];
        {
            const int oc = ocb + ((grp >> 1) << 3) + row;
            const int g  = 2*ks + (grp & 1);
            const uint32_t a = oc*256u + ((g ^ (oc & 7)) << 4);
            ldsm_x4(Bh, sb + FB_HI + a);
        }
#pragma unroll
        for (int mt = 0; mt < 2; mt++) {
            const int m = mbase + mt*16 + ((grp & 1) << 3) + row;
            const int g = 2*ks + (grp >> 1);
            const uint32_t a = m*256u + ((g ^ (m & 7)) << 4);
            uint32_t Ah[4], Al[4];
            ldsm_x4(Ah, sb + FA_HI + a);
            ldsm_x4(Al, sb + FA_LO + a);
#pragma unroll
            for (int f = 0; f < 2; f++) {
                mma16816(d[mt][f], Ah, Bh + 2*f);
                mma16816(d[mt][f], Al, Bh + 2*f);
            }
        }
    }
    __syncthreads();

    float* sf = reinterpret_cast<float*>(smem);    // [64][132]
#pragma unroll
    for (int mt = 0; mt < 2; mt++) {
#pragma unroll
        for (int f = 0; f < 2; f++) {
#pragma unroll
            for (int half = 0; half < 2; half++) {
                const int m = mbase + mt*16 + (lane >> 2) + half*8;
                const int c = ocb + f*8 + 2*(lane & 3);
                sf[(c+0)*132 + m] = d[mt][f][2*half+0];
                sf[(c+1)*132 + m] = d[mt][f][2*half+1];
            }
        }
    }
    __syncthreads();
    const int img = p0 >> 15, pix0 = p0 & (HW-1);
    for (int i = tid; i < 8192; i += 512) {
        const int c = i >> 7, px = i & 127;
        out[(size_t)img*CHW + (size_t)c*HW + pix0 + px] = sf[c*132 + px] + fb[c];
    }
}

// -----------------------------------------------------------------------------
extern "C" void kernel_launch(void* const* d_in, const int* in_sizes, int n_in,
                              void* d_out, int out_size)
{
    const float* xl    = (const float*)d_in[0];
    const float* xr    = (const float*)d_in[1];
    const int*   xxs   = (const int*)  d_in[2];
    const int*   yys   = (const int*)  d_in[3];
    const float* rb_w1 = (const float*)d_in[5];
    const float* rb_w2 = (const float*)d_in[6];
    const float* b1_w  = (const float*)d_in[7];
    const float* b1_b  = (const float*)d_in[8];
    const float* b2_w  = (const float*)d_in[9];
    const float* b2_b  = (const float*)d_in[10];
    const float* b3_w  = (const float*)d_in[11];
    const float* b3_b  = (const float*)d_in[12];
    const float* fus_w = (const float*)d_in[13];
    const float* fus_b = (const float*)d_in[14];
    float* out = (float*)d_out;

    static int attr_set = 0;
    if (!attr_set) {
        cudaFuncSetAttribute(conv_mma_kernel,
                             cudaFuncAttributeMaxDynamicSharedMemorySize, SMEM_CONV);
        cudaFuncSetAttribute(gemm_hmma<64>,
                             cudaFuncAttributeMaxDynamicSharedMemorySize, SMEM_GEMM);
        cudaFuncSetAttribute(gemm_hmma<128>,
                             cudaFuncAttributeMaxDynamicSharedMemorySize, SMEM_GEMM);
        cudaFuncSetAttribute(fuse_hmma,
                             cudaFuncAttributeMaxDynamicSharedMemorySize, SMEM_FUSE);
        attr_set = 1;
    }

    __half *p_in_hi, *p_in_lo, *p_mid_hi, *p_mid_lo;
    __half *p_w1h, *p_w2h;
    __half *p_bh, *p_bl, *p_wqh, *p_wsrh;
    float *p_Q, *p_S, *p_R;
    cudaGetSymbolAddress((void**)&p_in_hi,  g_in_hi);
    cudaGetSymbolAddress((void**)&p_in_lo,  g_in_lo);
    cudaGetSymbolAddress((void**)&p_mid_hi, g_mid_hi);
    cudaGetSymbolAddress((void**)&p_mid_lo, g_mid_lo);
    cudaGetSymbolAddress((void**)&p_w1h, g_w1_hi);
    cudaGetSymbolAddress((void**)&p_w2h, g_w2_hi);
    cudaGetSymbolAddress((void**)&p_bh,  g_buf_hi);
    cudaGetSymbolAddress((void**)&p_bl,  g_buf_lo);
    cudaGetSymbolAddress((void**)&p_wqh, g_wq_hi);
    cudaGetSymbolAddress((void**)&p_wsrh, g_wsr_hi);
    cudaGetSymbolAddress((void**)&p_Q, g_Q);
    cudaGetSymbolAddress((void**)&p_S, g_S);
    cudaGetSymbolAddress((void**)&p_R, g_R);

    prep_kernel<<<512, 256>>>(xl, xr);
    prep_w_kernel<<<144, 256>>>(rb_w1, rb_w2);
    prep_w2_kernel<<<80, 256>>>(b1_w, b2_w, b3_w, fus_w);

    conv_mma_kernel<<<256, 256, SMEM_CONV>>>(p_in_hi,  p_in_lo,  p_w1h, xl, xr, 0);
    conv_mma_kernel<<<256, 256, SMEM_CONV>>>(p_mid_hi, p_mid_lo, p_w2h, xl, xr, 1);

    gemm_hmma<64> <<<512, 512, SMEM_GEMM>>>(p_bh, p_bl, p_wqh,
                                            b1_b, b1_b, p_Q, p_Q);
    gemm_hmma<128><<<512, 512, SMEM_GEMM>>>(p_bh + (size_t)2*HW*64, p_bl + (size_t)2*HW*64,
                                            p_wsrh, b2_b, b3_b, p_S, p_R);

    attn_kernel<<<8192, 256>>>(xxs, yys, out + MOFF);
    fuse_hmma<<<512, 512, SMEM_FUSE>>>(fus_b, out);
}

// round 13
// speedup vs baseline: 4.2012x; 1.1147x over previous
#include <cuda_runtime.h>
#include <cuda_fp16.h>
#include <cstdint>

#define H_  128
#define W_  256
#define HW  32768
#define C_  64
#define CHW (C_*HW)          // 2,097,152
#define MOFF (2*CHW)         // out elements = 4,194,304

// ---------------- mma.sync / ldmatrix / cp.async helpers (sm_80+ PTX) --------
__device__ __forceinline__ uint32_t smem_u32(const void* p) {
    uint32_t a;
    asm("{ .reg .u64 t; cvta.to.shared.u64 t, %1; cvt.u32.u64 %0, t; }" : "=r"(a) : "l"(p));
    return a;
}
__device__ __forceinline__ void ldsm_x4(uint32_t* r, uint32_t addr) {
    asm volatile("ldmatrix.sync.aligned.m8n8.x4.shared.b16 {%0,%1,%2,%3}, [%4];"
        : "=r"(r[0]), "=r"(r[1]), "=r"(r[2]), "=r"(r[3]) : "r"(addr));
}
__device__ __forceinline__ void mma16816(float* d, const uint32_t* a, const uint32_t* b) {
    asm volatile("mma.sync.aligned.m16n8k16.row.col.f32.f16.f16.f32 "
        "{%0,%1,%2,%3}, {%4,%5,%6,%7}, {%8,%9}, {%0,%1,%2,%3};"
        : "+f"(d[0]), "+f"(d[1]), "+f"(d[2]), "+f"(d[3])
        : "r"(a[0]), "r"(a[1]), "r"(a[2]), "r"(a[3]), "r"(b[0]), "r"(b[1]));
}
#define CP16(dst, src, szr) \
    asm volatile("cp.async.cg.shared.global [%0], [%1], 16, %2;" \
        :: "r"(dst), "l"(src), "r"(szr) : "memory")
#define CP_WAIT_ALL() asm volatile("cp.async.wait_all;" ::: "memory")

// fp16 2-term split helpers: hi = rn(v), lo = rn(v - hi)
__device__ __forceinline__ uint32_t pack_hi(float v0, float v1, float& r0, float& r1) {
    __half h0 = __float2half_rn(v0);
    __half h1 = __float2half_rn(v1);
    r0 = v0 - __half2float(h0);
    r1 = v1 - __half2float(h1);
    return ((uint32_t)__half_as_ushort(h1) << 16) | __half_as_ushort(h0);
}
__device__ __forceinline__ uint32_t pack_lo(float r0, float r1) {
    return ((uint32_t)__half_as_ushort(__float2half_rn(r1)) << 16)
         | __half_as_ushort(__float2half_rn(r0));
}

// ---------------- scratch ----------------------------------------------------
__device__ __align__(16) __half g_in_hi [4*HW*C_];   // [img][y][x][ch]
__device__ __align__(16) __half g_in_lo [4*HW*C_];
__device__ __align__(16) __half g_mid_hi[4*HW*C_];
__device__ __align__(16) __half g_mid_lo[4*HW*C_];
__device__ __align__(16) __half g_buf_hi[4*HW*C_];   // residual block out
__device__ __align__(16) __half g_buf_lo[4*HW*C_];
__device__ __align__(16) __half g_att_hi[2*HW*C_];
__device__ __align__(16) __half g_att_lo[2*HW*C_];
__device__ __align__(16) __half g_w1_hi[9*64*64];    // [tap][oc][ch]
__device__ __align__(16) __half g_w2_hi[9*64*64];
__device__ __align__(16) __half g_wq_hi [64*64];     // [oc][ic]
__device__ __align__(16) __half g_wsr_hi[128*64];    // S then R
__device__ __align__(16) __half g_wf_hi [64*128];    // fuse [oc][ic]
__device__ __align__(16) float g_Q[2*HW*C_];         // [p][c] fp32
__device__ __align__(16) float g_S[2*HW*C_];
__device__ __align__(16) float g_R[2*HW*C_];

// ---------------- prep: fp32 NCHW -> fp16 hi/lo [img][y][x][ch] --------------
__global__ __launch_bounds__(256)
void prep_kernel(const float* __restrict__ xl, const float* __restrict__ xr)
{
    const int gp = blockIdx.x*256 + threadIdx.x;   // 0..4*HW-1
    const int n  = gp >> 15, pix = gp & (HW-1);
    const float* src = ((n < 2) ? (xl + n*CHW) : (xr + (n-2)*CHW)) + pix;

    uint32_t hb[32], lb[32];
#pragma unroll
    for (int j = 0; j < 32; j++) {
        float v0 = src[(size_t)(2*j)*HW];
        float v1 = src[(size_t)(2*j+1)*HW];
        float r0, r1;
        hb[j] = pack_hi(v0, v1, r0, r1);
        lb[j] = pack_lo(r0, r1);
    }
    uint4* dh = reinterpret_cast<uint4*>(g_in_hi + (size_t)gp*64);
    uint4* dl = reinterpret_cast<uint4*>(g_in_lo + (size_t)gp*64);
    const uint4* sh = reinterpret_cast<const uint4*>(hb);
    const uint4* sl = reinterpret_cast<const uint4*>(lb);
#pragma unroll
    for (int j = 0; j < 8; j++) { dh[j] = sh[j]; dl[j] = sl[j]; }
}

// ---------------- prep all weights (conv1, conv2, Q, S, R, fuse) -------------
__global__ __launch_bounds__(256)
void prep_w_all(const float* __restrict__ w1, const float* __restrict__ w2,
                const float* __restrict__ qw, const float* __restrict__ sw,
                const float* __restrict__ rw, const float* __restrict__ fw)
{
    const int i = blockIdx.x*256 + threadIdx.x;
    if (i < 9*4096) {
        const int tap = i >> 12, r = i & 4095;
        const int oc = r >> 6, ci = r & 63;
        const int src = (oc*64 + ci)*9 + tap;
        const int dst = (tap*64 + oc)*64 + ci;
        g_w1_hi[dst] = __float2half_rn(w1[src]);
        g_w2_hi[dst] = __float2half_rn(w2[src]);
    } else {
        const int j = i - 9*4096;
        if (j >= 20480) return;
        if (j < 4096)       g_wq_hi [j]             = __float2half_rn(qw[j]);
        else if (j < 8192)  g_wsr_hi[j - 4096]      = __float2half_rn(sw[j - 4096]);
        else if (j < 12288) g_wsr_hi[4096 + j-8192] = __float2half_rn(rw[j - 8192]);
        else                g_wf_hi [j - 12288]     = __float2half_rn(fw[j - 12288]);
    }
}

// ---------------- HMMA 3x3 conv: row-pair tiles + rolling A ring + cp.async --
// CTA = 256 thr (8 warps: 4 M x 2 N), strip = 64 px, segment = 8 rows (4 pairs)
#define APX2  66
#define AROW2 (APX2*128)               // 8448 bytes per plane per half
#define CA_HI 0u
#define CA_LO (4u*AROW2)               // 33792
#define CB_OFF (8u*AROW2)              // 67584
#define SMEM_CONV (CB_OFF + 16384u)    // 83968

__global__ __launch_bounds__(256, 2)
void conv_mma_kernel(const __half* __restrict__ in_hi,
                     const __half* __restrict__ in_lo,
                     const __half* __restrict__ w_hi,
                     const float* __restrict__ xl, const float* __restrict__ xr,
                     int layer)
{
    extern __shared__ __align__(16) char smem[];
    const uint32_t sb = smem_u32(smem);
    const int tid = threadIdx.x;
    const int lane = tid & 31, warp = tid >> 5;
    const int wm = warp & 3, wn = warp >> 2;
    const int mbase = wm*16, ocb = wn*32;
    const int grp = lane >> 3, row = lane & 7;

    const int cta = blockIdx.x;           // 256 CTAs = img(4) x strip(4) x seg(16)
    const int n  = cta >> 6;
    const int x0 = ((cta >> 4) & 3) * 64;
    const int y0 = (cta & 15) * 8;

    // async stage one input row gy into plane gy&3 (ignore-src zero fill OOB)
    auto stage_row = [&](int gy) {
        const uint32_t pl = (uint32_t)((gy + 4) & 3) * AROW2;
        const int cy = gy < 0 ? 0 : (gy >= H_ ? H_-1 : gy);
        for (int i = tid; i < 528; i += 256) {
            const int px = i >> 3, g = i & 7;
            const int gx = x0 + px - 1;
            const bool ok = ((unsigned)gy < (unsigned)H_) && ((unsigned)gx < (unsigned)W_);
            const int cx = gx < 0 ? 0 : (gx >= W_ ? W_-1 : gx);
            const size_t go = (((size_t)(n*H_ + cy))*W_ + cx)*64 + g*8;
            const uint32_t da = pl + px*128 + ((g ^ (px & 7)) << 4);
            const uint32_t sz = ok ? 16u : 0u;
            CP16(sb + CA_HI + da, in_hi + go, sz);
            CP16(sb + CA_LO + da, in_lo + go, sz);
        }
    };
    auto stage_B = [&](int tap, int buf) {
        const uint32_t bdst = CB_OFF + (uint32_t)buf*8192u;
        for (int i = tid; i < 512; i += 256) {
            const int oc = i >> 3, g = i & 7;
            const uint32_t da = bdst + oc*128 + ((g ^ (oc & 7)) << 4);
            const size_t so = ((size_t)(tap*64 + oc))*64 + g*8;
            CP16(sb + da, w_hi + so, 16u);
        }
    };

    stage_row(y0 - 1); stage_row(y0); stage_row(y0 + 1); stage_row(y0 + 2);
    stage_B(0, 0);
    CP_WAIT_ALL();
    __syncthreads();

    for (int p = 0; p < 4; p++) {
        const int yp = y0 + 2*p;

        float d[2][4][4];
#pragma unroll
        for (int t2 = 0; t2 < 2; t2++)
#pragma unroll
            for (int f = 0; f < 4; f++)
#pragma unroll
                for (int j = 0; j < 4; j++) d[t2][f][j] = 0.f;

        for (int tap = 0; tap < 9; tap++) {
            // async prefetches: next tap's B; next pair's rows at taps 3 & 6
            stage_B((tap + 1) % 9, (p + tap + 1) & 1);
            if (p < 3 && tap == 3) stage_row(yp + 3);
            if (p < 3 && tap == 6) stage_row(yp + 4);

            const int dy = tap/3 - 1, dx = tap%3 - 1;
            const uint32_t bcur = CB_OFF + (uint32_t)((p + tap) & 1)*8192u;

#pragma unroll
            for (int ks = 0; ks < 4; ks++) {
                uint32_t Bh[8];
                {
                    const int oc0 = ocb + ((grp >> 1) << 3) + row;
                    const int gB  = 2*ks + (grp & 1);
                    const uint32_t a0 = oc0*128u + ((gB ^ (oc0 & 7)) << 4);
                    ldsm_x4(Bh,     sb + bcur + a0);
                    const int oc1 = oc0 + 16;
                    const uint32_t a1 = oc1*128u + ((gB ^ (oc1 & 7)) << 4);
                    ldsm_x4(Bh + 4, sb + bcur + a1);
                }
#pragma unroll
                for (int t2 = 0; t2 < 2; t2++) {
                    const uint32_t pl = (uint32_t)((yp + t2 + dy + 4) & 3) * AROW2;
                    const int m  = mbase + ((grp & 1) << 3) + row;
                    const int gA = 2*ks + (grp >> 1);
                    const int px = m + dx + 1;
                    const uint32_t aoff = pl + px*128u + ((gA ^ (px & 7)) << 4);
                    uint32_t Ah[4], Al[4];
                    ldsm_x4(Ah, sb + CA_HI + aoff);
                    ldsm_x4(Al, sb + CA_LO + aoff);
#pragma unroll
                    for (int f = 0; f < 4; f++) {
                        mma16816(d[t2][f], Ah, Bh + 2*f);
                        mma16816(d[t2][f], Al, Bh + 2*f);
                    }
                }
            }
            CP_WAIT_ALL();
            __syncthreads();
        }

        // ---- epilogue (registers -> global; no smem) ------------------------
        const int mrow = (lane >> 2);
        const int cpair = 2*(lane & 3);
#pragma unroll
        for (int t2 = 0; t2 < 2; t2++) {
            const int y = yp + t2;
            if (layer == 0) {
#pragma unroll
                for (int f = 0; f < 4; f++) {
#pragma unroll
                    for (int half = 0; half < 2; half++) {
                        float v0 = d[t2][f][2*half+0], v1 = d[t2][f][2*half+1];
                        v0 = v0 > 0.f ? v0 : 0.1f*v0;
                        v1 = v1 > 0.f ? v1 : 0.1f*v1;
                        const int m = mbase + mrow + half*8;
                        const int c = ocb + f*8 + cpair;
                        const size_t o = (((size_t)(n*H_ + y))*W_ + x0 + m)*64 + c;
                        float r0, r1;
                        *reinterpret_cast<uint32_t*>(g_mid_hi + o) = pack_hi(v0, v1, r0, r1);
                        *reinterpret_cast<uint32_t*>(g_mid_lo + o) = pack_lo(r0, r1);
                    }
                }
            } else {
                const float* res = (n < 2) ? (xl + n*CHW) : (xr + (n-2)*CHW);
#pragma unroll
                for (int f = 0; f < 4; f++) {
#pragma unroll
                    for (int half = 0; half < 2; half++) {
                        const int m = mbase + mrow + half*8;
                        const int c = ocb + f*8 + cpair;
                        const int pix = y*W_ + x0 + m;
                        float v0 = d[t2][f][2*half+0] + res[(size_t)c*HW + pix];
                        float v1 = d[t2][f][2*half+1] + res[(size_t)(c+1)*HW + pix];
                        const size_t o = ((size_t)n*HW + pix)*64 + c;
                        float r0, r1;
                        *reinterpret_cast<uint32_t*>(g_buf_hi + o) = pack_hi(v0, v1, r0, r1);
                        *reinterpret_cast<uint32_t*>(g_buf_lo + o) = pack_lo(r0, r1);
                    }
                }
            }
        }
    }
}

// ---------------- generic HMMA GEMM: [65536 px] x NOC oc, K=64 ---------------
#define QA_HI 0u
#define QA_LO 16384u
#define QB_HI 32768u
#define SMEM_GEMM 49152u

template<int NOC>
__global__ __launch_bounds__(512, 2)
void gemm_hmma(const __half* __restrict__ a_hi,
               const __half* __restrict__ a_lo,
               const __half* __restrict__ w_hi,
               const float* __restrict__ biasA, const float* __restrict__ biasB,
               float* __restrict__ outA, float* __restrict__ outB)
{
    extern __shared__ __align__(16) char smem[];
    const uint32_t sb = smem_u32(smem);
    const int tid = threadIdx.x;
    const int lane = tid & 31, warp = tid >> 5;
    const int wm = warp & 3, wn = warp >> 2;
    constexpr int NW  = NOC/4;
    constexpr int L16 = NW/16;
    constexpr int F8  = NW/8;
    const int mbase = wm*32, ocb = wn*NW;
    const int grp = lane >> 3, row = lane & 7;
    const int p0 = blockIdx.x * 128;

    for (int i = tid; i < 1024; i += 512) {
        const int px = i >> 3, g = i & 7;
        const uint32_t da = px*128 + ((g ^ (px & 7)) << 4);
        const size_t so = (size_t)(p0+px)*64 + g*8;
        CP16(sb + QA_HI + da, a_hi + so, 16u);
        CP16(sb + QA_LO + da, a_lo + so, 16u);
    }
    for (int i = tid; i < NOC*8; i += 512) {
        const int oc = i >> 3, g = i & 7;
        const uint32_t da = oc*128 + ((g ^ (oc & 7)) << 4);
        const size_t so = (size_t)oc*64 + g*8;
        CP16(sb + QB_HI + da, w_hi + so, 16u);
    }
    CP_WAIT_ALL();
    __syncthreads();

    float d[2][F8][4];
#pragma unroll
    for (int mt = 0; mt < 2; mt++)
#pragma unroll
        for (int f = 0; f < F8; f++)
#pragma unroll
            for (int j = 0; j < 4; j++) d[mt][f][j] = 0.f;

#pragma unroll
    for (int ks = 0; ks < 4; ks++) {
        uint32_t Bh[4*L16];
#pragma unroll
        for (int l = 0; l < L16; l++) {
            const int oc = ocb + l*16 + ((grp >> 1) << 3) + row;
            const int g  = 2*ks + (grp & 1);
            const uint32_t a = oc*128u + ((g ^ (oc & 7)) << 4);
            ldsm_x4(Bh + 4*l, sb + QB_HI + a);
        }
#pragma unroll
        for (int mt = 0; mt < 2; mt++) {
            const int m = mbase + mt*16 + ((grp & 1) << 3) + row;
            const int g = 2*ks + (grp >> 1);
            const uint32_t a = m*128u + ((g ^ (m & 7)) << 4);
            uint32_t Ah[4], Al[4];
            ldsm_x4(Ah, sb + QA_HI + a);
            ldsm_x4(Al, sb + QA_LO + a);
#pragma unroll
            for (int f = 0; f < F8; f++) {
                mma16816(d[mt][f], Ah, Bh + 2*f);
                mma16816(d[mt][f], Al, Bh + 2*f);
            }
        }
    }

#pragma unroll
    for (int mt = 0; mt < 2; mt++) {
#pragma unroll
        for (int f = 0; f < F8; f++) {
#pragma unroll
            for (int half = 0; half < 2; half++) {
                const int m = mbase + mt*16 + (lane >> 2) + half*8;
                const int c = ocb + f*8 + 2*(lane & 3);
                const float* bias = (c < 64) ? biasA : biasB;
                const int col = c & 63;
                float v0 = d[mt][f][2*half+0] + bias[col];
                float v1 = d[mt][f][2*half+1] + bias[col+1];
                float* o = ((c < 64) ? outA : outB) + (size_t)(p0+m)*64 + col;
                *reinterpret_cast<float2*>(o) = make_float2(v0, v1);
            }
        }
    }
}

// ---------------- attention: warp per pixel, K = 16 --------------------------
__global__ __launch_bounds__(256)
void attn_kernel(const int* __restrict__ xxs, const int* __restrict__ yys,
                 float* __restrict__ outM)
{
    const unsigned FULL = 0xffffffffu;
    const int warp = threadIdx.x >> 5, lane = threadIdx.x & 31;
    const int gp = blockIdx.x*8 + warp;
    const int b  = gp >> 15;

    const float2 q = reinterpret_cast<const float2*>(g_Q + (size_t)gp*64)[lane];

    int idx = 0;
    if (lane < 16) {
        int i = gp*16 + lane;
        idx = xxs[i]*W_ + yys[i];
    }
    const float* Sb = g_S + (size_t)b*HW*64;
    const float* Rb = g_R + (size_t)b*HW*64;

    float myscore = -1e30f;
#pragma unroll
    for (int k = 0; k < 16; k++) {
        int id = __shfl_sync(FULL, idx, k);
        float2 kv = reinterpret_cast<const float2*>(Sb + (size_t)id*64)[lane];
        float s = q.x*kv.x + q.y*kv.y;
#pragma unroll
        for (int off = 16; off; off >>= 1) s += __shfl_xor_sync(FULL, s, off);
        if (lane == k) myscore = s;
    }
    float mx = myscore;
#pragma unroll
    for (int off = 8; off; off >>= 1) mx = fmaxf(mx, __shfl_xor_sync(FULL, mx, off));
    float e = expf(myscore - mx);
    float sum = e;
#pragma unroll
    for (int off = 8; off; off >>= 1) sum += __shfl_xor_sync(FULL, sum, off);
    float m = e / sum;

    float2 accv = make_float2(0.f, 0.f);
#pragma unroll
    for (int k = 0; k < 16; k++) {
        float mk = __shfl_sync(FULL, m, k);
        int   id = __shfl_sync(FULL, idx, k);
        float2 vv = reinterpret_cast<const float2*>(Rb + (size_t)id*64)[lane];
        accv.x = fmaf(mk, vv.x, accv.x);
        accv.y = fmaf(mk, vv.y, accv.y);
    }
    float r0, r1;
    const size_t o = (size_t)gp*64 + 2*lane;
    *reinterpret_cast<uint32_t*>(g_att_hi + o) = pack_hi(accv.x, accv.y, r0, r1);
    *reinterpret_cast<uint32_t*>(g_att_lo + o) = pack_lo(r0, r1);
    if (lane < 16) outM[(size_t)gp*16 + lane] = m;
}

// ---------------- fusion 1x1 HMMA: K=128 (attn 64 + x_left 64) -> 64 oc ------
#define FA_HI 0u
#define FA_LO 32768u
#define FB_HI 65536u
#define SMEM_FUSE 81920u

__global__ __launch_bounds__(512, 2)
void fuse_hmma(const float* __restrict__ fb, float* __restrict__ out)
{
    extern __shared__ __align__(16) char smem[];
    const uint32_t sb = smem_u32(smem);
    const int tid = threadIdx.x;
    const int lane = tid & 31, warp = tid >> 5;
    const int wm = warp & 3, wn = warp >> 2;
    const int mbase = wm*32, ocb = wn*16;
    const int grp = lane >> 3, row = lane & 7;
    const int p0 = blockIdx.x * 128;

    for (int i = tid; i < 2048; i += 512) {
        const int px = i >> 4, g = i & 15;
        const uint32_t da = px*256 + ((g ^ (px & 7)) << 4);
        const size_t so = (size_t)(p0+px)*64 + (g & 7)*8;
        const __half* sh = (g < 8) ? (g_att_hi + so) : (g_in_hi + so);
        const __half* sl = (g < 8) ? (g_att_lo + so) : (g_in_lo + so);
        CP16(sb + FA_HI + da, sh, 16u);
        CP16(sb + FA_LO + da, sl, 16u);
    }
    for (int i = tid; i < 1024; i += 512) {
        const int oc = i >> 4, g = i & 15;
        const uint32_t da = oc*256 + ((g ^ (oc & 7)) << 4);
        const size_t so = (size_t)oc*128 + g*8;
        CP16(sb + FB_HI + da, g_wf_hi + so, 16u);
    }
    CP_WAIT_ALL();
    __syncthreads();

    float d[2][2][4];
#pragma unroll
    for (int mt = 0; mt < 2; mt++)
#pragma unroll
        for (int f = 0; f < 2; f++)
#pragma unroll
            for (int j = 0; j < 4; j++) d[mt][f][j] = 0.f;

#pragma unroll
    for (int ks = 0; ks < 8; ks++) {
        uint32_t Bh[4];
        {
            const int oc = ocb + ((grp >> 1) << 3) + row;
            const int g  = 2*ks + (grp & 1);
            const uint32_t a = oc*256u + ((g ^ (oc & 7)) << 4);
            ldsm_x4(Bh, sb + FB_HI + a);
        }
#pragma unroll
        for (int mt = 0; mt < 2; mt++) {
            const int m = mbase + mt*16 + ((grp & 1) << 3) + row;
            const int g = 2*ks + (grp >> 1);
            const uint32_t a = m*256u + ((g ^ (m & 7)) << 4);
            uint32_t Ah[4], Al[4];
            ldsm_x4(Ah, sb + FA_HI + a);
            ldsm_x4(Al, sb + FA_LO + a);
#pragma unroll
            for (int f = 0; f < 2; f++) {
                mma16816(d[mt][f], Ah, Bh + 2*f);
                mma16816(d[mt][f], Al, Bh + 2*f);
            }
        }
    }
    __syncthreads();

    float* sf = reinterpret_cast<float*>(smem);    // [64][132]
#pragma unroll
    for (int mt = 0; mt < 2; mt++) {
#pragma unroll
        for (int f = 0; f < 2; f++) {
#pragma unroll
            for (int half = 0; half < 2; half++) {
                const int m = mbase + mt*16 + (lane >> 2) + half*8;
                const int c = ocb + f*8 + 2*(lane & 3);
                sf[(c+0)*132 + m] = d[mt][f][2*half+0];
                sf[(c+1)*132 + m] = d[mt][f][2*half+1];
            }
        }
    }
    __syncthreads();
    const int img = p0 >> 15, pix0 = p0 & (HW-1);
    for (int i = tid; i < 8192; i += 512) {
        const int c = i >> 7, px = i & 127;
        out[(size_t)img*CHW + (size_t)c*HW + pix0 + px] = sf[c*132 + px] + fb[c];
    }
}

// -----------------------------------------------------------------------------
extern "C" void kernel_launch(void* const* d_in, const int* in_sizes, int n_in,
                              void* d_out, int out_size)
{
    const float* xl    = (const float*)d_in[0];
    const float* xr    = (const float*)d_in[1];
    const int*   xxs   = (const int*)  d_in[2];
    const int*   yys   = (const int*)  d_in[3];
    const float* rb_w1 = (const float*)d_in[5];
    const float* rb_w2 = (const float*)d_in[6];
    const float* b1_w  = (const float*)d_in[7];
    const float* b1_b  = (const float*)d_in[8];
    const float* b2_w  = (const float*)d_in[9];
    const float* b2_b  = (const float*)d_in[10];
    const float* b3_w  = (const float*)d_in[11];
    const float* b3_b  = (const float*)d_in[12];
    const float* fus_w = (const float*)d_in[13];
    const float* fus_b = (const float*)d_in[14];
    float* out = (float*)d_out;

    static int attr_set = 0;
    if (!attr_set) {
        cudaFuncSetAttribute(conv_mma_kernel,
                             cudaFuncAttributeMaxDynamicSharedMemorySize, SMEM_CONV);
        cudaFuncSetAttribute(gemm_hmma<64>,
                             cudaFuncAttributeMaxDynamicSharedMemorySize, SMEM_GEMM);
        cudaFuncSetAttribute(gemm_hmma<128>,
                             cudaFuncAttributeMaxDynamicSharedMemorySize, SMEM_GEMM);
        cudaFuncSetAttribute(fuse_hmma,
                             cudaFuncAttributeMaxDynamicSharedMemorySize, SMEM_FUSE);
        attr_set = 1;
    }

    __half *p_in_hi, *p_in_lo, *p_mid_hi, *p_mid_lo;
    __half *p_w1h, *p_w2h;
    __half *p_bh, *p_bl, *p_wqh, *p_wsrh;
    float *p_Q, *p_S, *p_R;
    cudaGetSymbolAddress((void**)&p_in_hi,  g_in_hi);
    cudaGetSymbolAddress((void**)&p_in_lo,  g_in_lo);
    cudaGetSymbolAddress((void**)&p_mid_hi, g_mid_hi);
    cudaGetSymbolAddress((void**)&p_mid_lo, g_mid_lo);
    cudaGetSymbolAddress((void**)&p_w1h, g_w1_hi);
    cudaGetSymbolAddress((void**)&p_w2h, g_w2_hi);
    cudaGetSymbolAddress((void**)&p_bh,  g_buf_hi);
    cudaGetSymbolAddress((void**)&p_bl,  g_buf_lo);
    cudaGetSymbolAddress((void**)&p_wqh, g_wq_hi);
    cudaGetSymbolAddress((void**)&p_wsrh, g_wsr_hi);
    cudaGetSymbolAddress((void**)&p_Q, g_Q);
    cudaGetSymbolAddress((void**)&p_S, g_S);
    cudaGetSymbolAddress((void**)&p_R, g_R);

    prep_kernel<<<512, 256>>>(xl, xr);
    prep_w_all<<<224, 256>>>(rb_w1, rb_w2, b1_w, b2_w, b3_w, fus_w);

    conv_mma_kernel<<<256, 256, SMEM_CONV>>>(p_in_hi,  p_in_lo,  p_w1h, xl, xr, 0);
    conv_mma_kernel<<<256, 256, SMEM_CONV>>>(p_mid_hi, p_mid_lo, p_w2h, xl, xr, 1);

    gemm_hmma<64> <<<512, 512, SMEM_GEMM>>>(p_bh, p_bl, p_wqh,
                                            b1_b, b1_b, p_Q, p_Q);
    gemm_hmma<128><<<512, 512, SMEM_GEMM>>>(p_bh + (size_t)2*HW*64, p_bl + (size_t)2*HW*64,
                                            p_wsrh, b2_b, b3_b, p_S, p_R);

    attn_kernel<<<8192, 256>>>(xxs, yys, out + MOFF);
    fuse_hmma<<<512, 512, SMEM_FUSE>>>(fus_b, out);
}